// round 9
// baseline (speedup 1.0000x reference)
#include <cuda_runtime.h>
#include <cuda_bf16.h>
#include <cstdint>

#define NMAX 100000
#define EMAX 600000

// Scratch (static device globals — allocation-free per harness rules)
__device__ __align__(16) float g_ylr[NMAX * 128];  // projected [y_l | y_r]
__device__ __align__(16) float g_x[NMAX * 64];     // layer activations
__device__ __align__(16) unsigned short g_wth[128 * 128];  // W0 hi bf16, n-major [n][k]
__device__ __align__(16) unsigned short g_wtl[128 * 128];  // W0 lo bf16, n-major [n][k]
__device__ int g_cnt[NMAX];
__device__ int g_off[NMAX];
__device__ int g_cur[NMAX];
__device__ int g_esrc[EMAX];
__device__ int g_bsum[512];

// ---------------------------------------------------------------------------
// cp.async + packed fma helpers (used by the f32x2 GEMM only)
// ---------------------------------------------------------------------------
__device__ __forceinline__ void cp_async16(uint32_t dst, const void* src, int src_bytes) {
    asm volatile("cp.async.cg.shared.global [%0], [%1], 16, %2;\n"
                 :: "r"(dst), "l"(src), "r"(src_bytes));
}
__device__ __forceinline__ void cp_commit() { asm volatile("cp.async.commit_group;\n"); }
template <int N>
__device__ __forceinline__ void cp_wait() { asm volatile("cp.async.wait_group %0;\n" :: "n"(N)); }

__device__ __forceinline__ void fma_x2(unsigned long long& acc, unsigned long long a2,
                                       unsigned long long b2) {
    asm("fma.rn.f32x2 %0, %1, %2, %0;" : "+l"(acc) : "l"(a2), "l"(b2));
}
__device__ __forceinline__ unsigned long long dup_f32(float a) {
    unsigned long long r;
    asm("mov.b64 %0, {%1, %1};" : "=l"(r) : "f"(a));
    return r;
}

// ---------------------------------------------------------------------------
// CSR build
// ---------------------------------------------------------------------------
__global__ void zero_int(int* __restrict__ p, int n) {
    int i = blockIdx.x * blockDim.x + threadIdx.x;
    if (i < n) p[i] = 0;
}

__global__ void hist_kernel(const int* __restrict__ dst, int* __restrict__ cnt, int E) {
    int i = blockIdx.x * blockDim.x + threadIdx.x;
    if (i < E) atomicAdd(&cnt[dst[i]], 1);
}

__device__ __forceinline__ int block_exscan_512(int v, int tid, int* warp_sums, int* total) {
    int lane = tid & 31, wid = tid >> 5;
    int inc = v;
#pragma unroll
    for (int st = 1; st < 32; st <<= 1) {
        int t = __shfl_up_sync(0xFFFFFFFFu, inc, st);
        if (lane >= st) inc += t;
    }
    if (lane == 31) warp_sums[wid] = inc;
    __syncthreads();
    if (wid == 0) {
        int ws = (lane < 16) ? warp_sums[lane] : 0;
#pragma unroll
        for (int st = 1; st < 16; st <<= 1) {
            int t = __shfl_up_sync(0xFFFFFFFFu, ws, st);
            if (lane >= st) ws += t;
        }
        if (lane < 16) warp_sums[lane] = ws;
    }
    __syncthreads();
    int base = (wid > 0) ? warp_sums[wid - 1] : 0;
    if (total) *total = warp_sums[15];
    return base + inc - v;
}

__global__ void scan_block(const int* __restrict__ cnt, int* __restrict__ off,
                           int* __restrict__ bsum, int n) {
    __shared__ int ws[16];
    int i = blockIdx.x * 512 + threadIdx.x;
    int v = (i < n) ? cnt[i] : 0;
    int total;
    int ex = block_exscan_512(v, threadIdx.x, ws, &total);
    if (i < n) off[i] = ex;
    if (threadIdx.x == 0) bsum[blockIdx.x] = total;
}

__global__ void scan_sums(int* __restrict__ bsum, int nb) {
    __shared__ int ws[16];
    int v = (threadIdx.x < nb) ? bsum[threadIdx.x] : 0;
    int ex = block_exscan_512(v, threadIdx.x, ws, nullptr);
    if (threadIdx.x < nb) bsum[threadIdx.x] = ex;
}

__global__ void scan_add(int* __restrict__ off, const int* __restrict__ bsum,
                         int* __restrict__ cur, int n) {
    int i = blockIdx.x * 512 + threadIdx.x;
    if (i < n) {
        int o = off[i] + bsum[blockIdx.x];
        off[i] = o;
        cur[i] = o;
    }
}

__global__ void fill_kernel(const int* __restrict__ src, const int* __restrict__ dst,
                            int* __restrict__ cur, int* __restrict__ esrc, int E) {
    int e = blockIdx.x * blockDim.x + threadIdx.x;
    if (e < E) {
        int p = atomicAdd(&cur[dst[e]], 1);
        esrc[p] = src[e];
    }
}

// ---------------------------------------------------------------------------
// W0 combined [k=128][n=128] -> transposed n-major bf16 hi/lo: wt[n*128 + k]
// ---------------------------------------------------------------------------
__global__ void cvt_w_kernel(const float* __restrict__ wl, const float* __restrict__ wr,
                             unsigned short* __restrict__ wth, unsigned short* __restrict__ wtl) {
    int i = blockIdx.x * blockDim.x + threadIdx.x;
    if (i >= 128 * 128) return;
    int nn = i >> 7, k = i & 127;
    float w = (nn < 64) ? wl[k * 64 + nn] : wr[k * 64 + (nn - 64)];
    __nv_bfloat16 h = __float2bfloat16(w);
    __nv_bfloat16 l = __float2bfloat16(w - __bfloat162float(h));
    wth[i] = *reinterpret_cast<unsigned short*>(&h);
    wtl[i] = *reinterpret_cast<unsigned short*>(&l);
}

// ---------------------------------------------------------------------------
// layer-0 tensor-core GEMM: ylr[n x 128] = X[n x 128] @ W[128 x 128]
// 3-term bf16 split, fp32 accum, mma.m16n8k16. X loaded as fp32 directly and
// split to hi/lo bf16 in-kernel (no separate conversion pass / scratch).
// Explicit LDS fragment loads (PTX thread mappings), single staged tile.
// Block: 256 thr (8 warps = 4m x 2n), BM=128, full K resident in smem.
// ---------------------------------------------------------------------------
__device__ __forceinline__ void mma16816(float* d, const unsigned* a,
                                         unsigned b0, unsigned b1) {
    asm volatile(
        "mma.sync.aligned.m16n8k16.row.col.f32.bf16.bf16.f32 "
        "{%0,%1,%2,%3}, {%4,%5,%6,%7}, {%8,%9}, {%0,%1,%2,%3};"
        : "+f"(d[0]), "+f"(d[1]), "+f"(d[2]), "+f"(d[3])
        : "r"(a[0]), "r"(a[1]), "r"(a[2]), "r"(a[3]), "r"(b0), "r"(b1));
}

__device__ __forceinline__ unsigned pack2_hi(float a, float b) {
    __nv_bfloat162 t;
    t.x = __float2bfloat16(a);
    t.y = __float2bfloat16(b);
    return *reinterpret_cast<unsigned*>(&t);
}

__global__ void __launch_bounds__(256)
mma_proj0(const float* __restrict__ x, const unsigned short* __restrict__ wth,
          const unsigned short* __restrict__ wtl, float* __restrict__ ylr, int n) {
    constexpr int S = 136;  // smem row stride in halves (272B; 68 words == 4 mod 32)
    extern __shared__ __align__(16) unsigned short smu[];
    unsigned short* sXh = smu;              // [128][S]
    unsigned short* sXl = sXh + 128 * S;
    unsigned short* sWh = sXl + 128 * S;    // n-major [n][k]
    unsigned short* sWl = sWh + 128 * S;

    const int tid = threadIdx.x;
    const int lane = tid & 31;
    const int warp = tid >> 5;
    const int warpm = warp >> 1;   // 0..3: 32 rows each
    const int warpn = warp & 1;    // 0..1: 64 cols each
    const int nb = blockIdx.x * 128;
    const int mrem = n - nb;

    // stage X: 128 rows x 32 float4-chunks; convert fp32 -> bf16 hi/lo inline
    for (int idx = tid; idx < 128 * 32; idx += 256) {
        int r = idx >> 5, cc = (idx & 31) * 4;  // cc: float offset within row
        float4 v = make_float4(0.f, 0.f, 0.f, 0.f);
        if (r < mrem)
            v = *reinterpret_cast<const float4*>(&x[(size_t)(nb + r) * 128 + cc]);
        __nv_bfloat16 h0 = __float2bfloat16(v.x), h1 = __float2bfloat16(v.y);
        __nv_bfloat16 h2 = __float2bfloat16(v.z), h3 = __float2bfloat16(v.w);
        uint2 ph, pl;
        __nv_bfloat162 t;
        t.x = h0; t.y = h1; ph.x = *reinterpret_cast<unsigned*>(&t);
        t.x = h2; t.y = h3; ph.y = *reinterpret_cast<unsigned*>(&t);
        pl.x = pack2_hi(v.x - __bfloat162float(h0), v.y - __bfloat162float(h1));
        pl.y = pack2_hi(v.z - __bfloat162float(h2), v.w - __bfloat162float(h3));
        *reinterpret_cast<uint2*>(&sXh[r * S + cc]) = ph;
        *reinterpret_cast<uint2*>(&sXl[r * S + cc]) = pl;
    }
    // stage W: 128 rows x 16 uint4-chunks per array
    for (int idx = tid; idx < 128 * 16; idx += 256) {
        int r = idx >> 4, c = (idx & 15) * 8;
        *reinterpret_cast<uint4*>(&sWh[r * S + c]) =
            *reinterpret_cast<const uint4*>(&wth[r * 128 + c]);
        *reinterpret_cast<uint4*>(&sWl[r * S + c]) =
            *reinterpret_cast<const uint4*>(&wtl[r * 128 + c]);
    }
    __syncthreads();

    const int g = lane >> 2;        // 0..7
    const int t2 = (lane & 3) * 2;  // 0,2,4,6

    float acc[2][8][4];
#pragma unroll
    for (int mt = 0; mt < 2; ++mt)
#pragma unroll
        for (int nt = 0; nt < 8; ++nt)
#pragma unroll
            for (int t = 0; t < 4; ++t) acc[mt][nt][t] = 0.f;

#pragma unroll
    for (int s = 0; s < 8; ++s) {
        const int k0 = s * 16;
        unsigned ah[2][4], al[2][4];
#pragma unroll
        for (int mt = 0; mt < 2; ++mt) {
            int r = warpm * 32 + mt * 16 + g;
            ah[mt][0] = *reinterpret_cast<const unsigned*>(&sXh[r * S + k0 + t2]);
            ah[mt][1] = *reinterpret_cast<const unsigned*>(&sXh[(r + 8) * S + k0 + t2]);
            ah[mt][2] = *reinterpret_cast<const unsigned*>(&sXh[r * S + k0 + t2 + 8]);
            ah[mt][3] = *reinterpret_cast<const unsigned*>(&sXh[(r + 8) * S + k0 + t2 + 8]);
            al[mt][0] = *reinterpret_cast<const unsigned*>(&sXl[r * S + k0 + t2]);
            al[mt][1] = *reinterpret_cast<const unsigned*>(&sXl[(r + 8) * S + k0 + t2]);
            al[mt][2] = *reinterpret_cast<const unsigned*>(&sXl[r * S + k0 + t2 + 8]);
            al[mt][3] = *reinterpret_cast<const unsigned*>(&sXl[(r + 8) * S + k0 + t2 + 8]);
        }
#pragma unroll
        for (int nt = 0; nt < 8; ++nt) {
            int nn = warpn * 64 + nt * 8 + g;
            unsigned bh0 = *reinterpret_cast<const unsigned*>(&sWh[nn * S + k0 + t2]);
            unsigned bh1 = *reinterpret_cast<const unsigned*>(&sWh[nn * S + k0 + t2 + 8]);
            unsigned bl0 = *reinterpret_cast<const unsigned*>(&sWl[nn * S + k0 + t2]);
            unsigned bl1 = *reinterpret_cast<const unsigned*>(&sWl[nn * S + k0 + t2 + 8]);
#pragma unroll
            for (int mt = 0; mt < 2; ++mt) {
                mma16816(acc[mt][nt], ah[mt], bh0, bh1);  // Xh*Wh
                mma16816(acc[mt][nt], al[mt], bh0, bh1);  // Xl*Wh
                mma16816(acc[mt][nt], ah[mt], bl0, bl1);  // Xh*Wl
            }
        }
    }

#pragma unroll
    for (int mt = 0; mt < 2; ++mt) {
#pragma unroll
        for (int nt = 0; nt < 8; ++nt) {
            int col = warpn * 64 + nt * 8 + t2;
            int node0 = nb + warpm * 32 + mt * 16 + g;
            int node1 = node0 + 8;
            if (node0 < n) {
                float2 v = make_float2(acc[mt][nt][0], acc[mt][nt][1]);
                *reinterpret_cast<float2*>(&ylr[(size_t)node0 * 128 + col]) = v;
            }
            if (node1 < n) {
                float2 v = make_float2(acc[mt][nt][2], acc[mt][nt][3]);
                *reinterpret_cast<float2*>(&ylr[(size_t)node1 * 128 + col]) = v;
            }
        }
    }
}

// ---------------------------------------------------------------------------
// projection GEMM (packed f32x2) — layer 1
// ---------------------------------------------------------------------------
template <int K, int NC, int BM, int BK, int MINBLK>
__global__ void __launch_bounds__((BM / 8) * (NC / 8), MINBLK)
sgemm_proj_x2(const float* __restrict__ x, const float* __restrict__ wl,
              const float* __restrict__ wr, float* __restrict__ ylr, int n) {
    constexpr int TM = 8;
    constexpr int PAD = 4;
    constexpr int F = NC / 2;
    constexpr int NTH = (BM / TM) * (NC / 8);
    constexpr int KT = K / BK;
    constexpr int XS = BK + PAD;

    extern __shared__ float smf[];
    float* sX = smf;
    float* sB = smf + 2 * BM * XS;

    const int tid = threadIdx.x;
    const int nb = blockIdx.x * BM;
    const int mrem = n - nb;

    auto load_tile = [&](int kb, int buf) {
        const int k0 = kb * BK;
        float* sXb = sX + buf * BM * XS;
        float* sBb = sB + buf * BK * NC;
        for (int idx = tid; idx < BM * BK / 4; idx += NTH) {
            int m = idx / (BK / 4);
            int kc = idx % (BK / 4);
            uint32_t dst = (uint32_t)__cvta_generic_to_shared(&sXb[m * XS + kc * 4]);
            int mm = (m < mrem) ? m : 0;
            const float* src = x + (size_t)(nb + mm) * K + k0 + kc * 4;
            cp_async16(dst, src, (m < mrem) ? 16 : 0);
        }
        for (int idx = tid; idx < BK * NC / 4; idx += NTH) {
            int kr = idx / (NC / 4);
            int j = (idx % (NC / 4)) * 4;
            const float* src = (j < F) ? (wl + (size_t)(kr + k0) * F + j)
                                       : (wr + (size_t)(kr + k0) * F + (j - F));
            uint32_t dst = (uint32_t)__cvta_generic_to_shared(&sBb[kr * NC + j]);
            cp_async16(dst, src, 16);
        }
    };

    load_tile(0, 0);
    cp_commit();

    constexpr int CG = NC / 8;
    const int tj = tid % CG;
    const int ti = tid / CG;
    const int m0 = ti * TM;
    const int jA = tj * 4;
    const int jB = jA + F;

    unsigned long long acc[TM][4];
#pragma unroll
    for (int i = 0; i < TM; ++i)
#pragma unroll
        for (int t = 0; t < 4; ++t) acc[i][t] = 0ull;

    for (int kb = 0; kb < KT; ++kb) {
        if (kb + 1 < KT) {
            load_tile(kb + 1, (kb + 1) & 1);
            cp_commit();
            cp_wait<1>();
        } else {
            cp_wait<0>();
        }
        __syncthreads();

        const float* bx = sX + (kb & 1) * BM * XS;
        const float* bb = sB + (kb & 1) * BK * NC;
#pragma unroll
        for (int k = 0; k < BK; ++k) {
            ulonglong2 bp0 = *reinterpret_cast<const ulonglong2*>(&bb[k * NC + jA]);
            ulonglong2 bp1 = *reinterpret_cast<const ulonglong2*>(&bb[k * NC + jB]);
#pragma unroll
            for (int i = 0; i < TM; ++i) {
                unsigned long long a2 = dup_f32(bx[(m0 + i) * XS + k]);
                fma_x2(acc[i][0], a2, bp0.x);
                fma_x2(acc[i][1], a2, bp0.y);
                fma_x2(acc[i][2], a2, bp1.x);
                fma_x2(acc[i][3], a2, bp1.y);
            }
        }
        __syncthreads();
    }

#pragma unroll
    for (int i = 0; i < TM; ++i) {
        int node = nb + m0 + i;
        if (node < n) {
            ulonglong2 v0, v1;
            v0.x = acc[i][0]; v0.y = acc[i][1];
            v1.x = acc[i][2]; v1.y = acc[i][3];
            *reinterpret_cast<ulonglong2*>(&ylr[(size_t)node * NC + jA]) = v0;
            *reinterpret_cast<ulonglong2*>(&ylr[(size_t)node * NC + jB]) = v1;
        }
    }
}

// ---------------------------------------------------------------------------
// per-node projection for small layers
// ---------------------------------------------------------------------------
template <int K, int F>
__global__ void proj_pernode(const float* __restrict__ x, const float* __restrict__ wl,
                             const float* __restrict__ wr, float* __restrict__ ylr, int n) {
    constexpr int NC = 2 * F;
    __shared__ float sB[K * NC];
    for (int i = threadIdx.x; i < K * NC; i += blockDim.x) {
        int k = i / NC, j = i % NC;
        sB[i] = (j < F) ? wl[k * F + j] : wr[k * F + (j - F)];
    }
    __syncthreads();

    int node = blockIdx.x * blockDim.x + threadIdx.x;
    if (node >= n) return;

    float xv[K];
    const float4* xr = reinterpret_cast<const float4*>(x + (size_t)node * K);
#pragma unroll
    for (int c = 0; c < K / 4; ++c) {
        float4 v = xr[c];
        xv[c * 4 + 0] = v.x; xv[c * 4 + 1] = v.y; xv[c * 4 + 2] = v.z; xv[c * 4 + 3] = v.w;
    }
    float acc[NC];
#pragma unroll
    for (int j = 0; j < NC; ++j) acc[j] = 0.f;
#pragma unroll
    for (int k = 0; k < K; ++k) {
        float a = xv[k];
#pragma unroll
        for (int j = 0; j < NC; ++j) acc[j] = fmaf(a, sB[k * NC + j], acc[j]);
    }
    float4* o = reinterpret_cast<float4*>(ylr + (size_t)node * NC);
#pragma unroll
    for (int c = 0; c < NC / 4; ++c)
        o[c] = make_float4(acc[c * 4], acc[c * 4 + 1], acc[c * 4 + 2], acc[c * 4 + 3]);
}

__global__ void proj3_pernode(const float* __restrict__ x, const float* __restrict__ wl,
                              const float* __restrict__ wr, float* __restrict__ ylr3, int n) {
    __shared__ float swl[16 * 9];
    __shared__ float swr[16 * 9];
    for (int i = threadIdx.x; i < 144; i += blockDim.x) {
        swl[i] = wl[i];
        swr[i] = wr[i];
    }
    __syncthreads();

    int node = blockIdx.x * blockDim.x + threadIdx.x;
    if (node >= n) return;

    float xv[16];
    const float4* xr = reinterpret_cast<const float4*>(x + (size_t)node * 16);
#pragma unroll
    for (int c = 0; c < 4; ++c) {
        float4 v = xr[c];
        xv[c * 4 + 0] = v.x; xv[c * 4 + 1] = v.y; xv[c * 4 + 2] = v.z; xv[c * 4 + 3] = v.w;
    }
    float al[9], ar[9];
#pragma unroll
    for (int j = 0; j < 9; ++j) { al[j] = 0.f; ar[j] = 0.f; }
#pragma unroll
    for (int k = 0; k < 16; ++k) {
        float a = xv[k];
#pragma unroll
        for (int j = 0; j < 9; ++j) {
            al[j] = fmaf(a, swl[k * 9 + j], al[j]);
            ar[j] = fmaf(a, swr[k * 9 + j], ar[j]);
        }
    }
    float4* o = reinterpret_cast<float4*>(ylr3 + (size_t)node * 32);
    o[0] = make_float4(al[0], al[1], al[2], al[3]);
    o[1] = make_float4(al[4], al[5], al[6], al[7]);
    o[2] = make_float4(al[8], 0.f, 0.f, 0.f);
    o[3] = make_float4(0.f, 0.f, 0.f, 0.f);
    o[4] = make_float4(ar[0], ar[1], ar[2], ar[3]);
    o[5] = make_float4(ar[4], ar[5], ar[6], ar[7]);
    ylr3[(size_t)node * 32 + 24] = ar[8];
}

// ---------------------------------------------------------------------------
// gather + combine (fused): warp per node.
// ---------------------------------------------------------------------------
template <int F, bool RELU>
__global__ void gather_combine(const float* __restrict__ ylr, const int* __restrict__ esrc,
                               const int* __restrict__ off, const int* __restrict__ cnt,
                               const float* __restrict__ bias, float* __restrict__ out, int n) {
    constexpr int CH = F / 4;
    constexpr int EPW = 32 / CH;
    int w = (blockIdx.x * blockDim.x + threadIdx.x) >> 5;
    if (w >= n) return;
    int lane = threadIdx.x & 31;
    int c = lane % CH, g = lane / CH;
    int start = off[w], deg = cnt[w];

    float4 acc = make_float4(0.f, 0.f, 0.f, 0.f);
    const float4* y4 = reinterpret_cast<const float4*>(ylr);
    for (int j = g; j < deg; j += EPW) {
        int s = __ldg(esrc + start + j);
        float4 v = y4[(size_t)s * (F / 2) + c];
        acc.x += v.x; acc.y += v.y; acc.z += v.z; acc.w += v.w;
    }
#pragma unroll
    for (int st = 16; st >= CH; st >>= 1) {
        acc.x += __shfl_xor_sync(0xFFFFFFFFu, acc.x, st);
        acc.y += __shfl_xor_sync(0xFFFFFFFFu, acc.y, st);
        acc.z += __shfl_xor_sync(0xFFFFFFFFu, acc.z, st);
        acc.w += __shfl_xor_sync(0xFFFFFFFFu, acc.w, st);
    }
    if (lane < CH) {
        float iv = __frcp_rn(fmaxf((float)deg, 1.0f));
        float4 r = y4[(size_t)w * (F / 2) + (F / 4) + c];
        float4 b = reinterpret_cast<const float4*>(bias)[c];
        float4 v;
        v.x = fmaf(acc.x, iv, r.x) + b.x;
        v.y = fmaf(acc.y, iv, r.y) + b.y;
        v.z = fmaf(acc.z, iv, r.z) + b.z;
        v.w = fmaf(acc.w, iv, r.w) + b.w;
        if (RELU) {
            v.x = fmaxf(v.x, 0.f); v.y = fmaxf(v.y, 0.f);
            v.z = fmaxf(v.z, 0.f); v.w = fmaxf(v.w, 0.f);
        }
        reinterpret_cast<float4*>(out)[(size_t)w * CH + c] = v;
    }
}

__global__ void gather9(const float* __restrict__ ylr3, const int* __restrict__ esrc,
                        const int* __restrict__ off, const int* __restrict__ cnt,
                        const float* __restrict__ bias, float* __restrict__ out, int n) {
    int w = (blockIdx.x * blockDim.x + threadIdx.x) >> 5;
    if (w >= n) return;
    int lane = threadIdx.x & 31;
    int c = lane % 4, g = lane / 4;
    int start = off[w], deg = cnt[w];

    float4 acc = make_float4(0.f, 0.f, 0.f, 0.f);
    const float4* y4 = reinterpret_cast<const float4*>(ylr3);
    for (int j = g; j < deg; j += 8) {
        int s = __ldg(esrc + start + j);
        float4 v = y4[(size_t)s * 8 + c];
        acc.x += v.x; acc.y += v.y; acc.z += v.z; acc.w += v.w;
    }
#pragma unroll
    for (int st = 16; st >= 4; st >>= 1) {
        acc.x += __shfl_xor_sync(0xFFFFFFFFu, acc.x, st);
        acc.y += __shfl_xor_sync(0xFFFFFFFFu, acc.y, st);
        acc.z += __shfl_xor_sync(0xFFFFFFFFu, acc.z, st);
        acc.w += __shfl_xor_sync(0xFFFFFFFFu, acc.w, st);
    }
    if (lane < 4) {
        float iv = __frcp_rn(fmaxf((float)deg, 1.0f));
        float a[4] = {acc.x, acc.y, acc.z, acc.w};
#pragma unroll
        for (int t = 0; t < 4; ++t) {
            int j = c * 4 + t;
            if (j < 9) {
                float yr = ylr3[(size_t)w * 32 + 16 + j];
                out[(size_t)w * 9 + j] = fmaf(a[t], iv, yr + __ldg(bias + j));
            }
        }
    }
}

// ---------------------------------------------------------------------------
// launch
// ---------------------------------------------------------------------------
extern "C" void kernel_launch(void* const* d_in, const int* in_sizes, int n_in,
                              void* d_out, int out_size) {
    const float* emb = (const float*)d_in[0];
    const int* ei = (const int*)d_in[1];
    const float* wl0 = (const float*)d_in[3];
    const float* wr0 = (const float*)d_in[4];
    const float* b0  = (const float*)d_in[5];
    const float* wl1 = (const float*)d_in[6];
    const float* wr1 = (const float*)d_in[7];
    const float* b1  = (const float*)d_in[8];
    const float* wl2 = (const float*)d_in[9];
    const float* wr2 = (const float*)d_in[10];
    const float* b2  = (const float*)d_in[11];
    const float* wl3 = (const float*)d_in[12];
    const float* wr3 = (const float*)d_in[13];
    const float* b3  = (const float*)d_in[14];
    float* out = (float*)d_out;

    const int n = in_sizes[0] / 128;
    const int E = in_sizes[1] / 2;
    const int* src = ei;
    const int* dst = ei + E;

    float *ylr, *xbuf;
    unsigned short *wth, *wtl;
    int *cnt, *off, *cur, *esrc, *bsum;
    cudaGetSymbolAddress((void**)&ylr, g_ylr);
    cudaGetSymbolAddress((void**)&xbuf, g_x);
    cudaGetSymbolAddress((void**)&wth, g_wth);
    cudaGetSymbolAddress((void**)&wtl, g_wtl);
    cudaGetSymbolAddress((void**)&cnt, g_cnt);
    cudaGetSymbolAddress((void**)&off, g_off);
    cudaGetSymbolAddress((void**)&cur, g_cur);
    cudaGetSymbolAddress((void**)&esrc, g_esrc);
    cudaGetSymbolAddress((void**)&bsum, g_bsum);

    auto cdiv = [](int a, int b) { return (a + b - 1) / b; };
    const int TB = 256;
    const int nb = cdiv(n, 512);

    const int SM_MMA = 4 * 128 * 136 * 2;               // 139264
    const int SM1 = (2 * 128 * 36 + 2 * 32 * 64) * 4;   // 53248
    cudaFuncSetAttribute((const void*)mma_proj0,
                         cudaFuncAttributeMaxDynamicSharedMemorySize, SM_MMA);
    cudaFuncSetAttribute((const void*)sgemm_proj_x2<64, 64, 128, 32, 4>,
                         cudaFuncAttributeMaxDynamicSharedMemorySize, SM1);

    static cudaStream_t s2 = nullptr;
    static cudaEvent_t evFork = nullptr, evJoin = nullptr;
    if (!s2) {
        cudaStreamCreateWithFlags(&s2, cudaStreamNonBlocking);
        cudaEventCreateWithFlags(&evFork, cudaEventDisableTiming);
        cudaEventCreateWithFlags(&evJoin, cudaEventDisableTiming);
    }

    // ---- fork: CSR build on s2 ----
    cudaEventRecord(evFork, 0);
    cudaStreamWaitEvent(s2, evFork, 0);

    zero_int<<<cdiv(n, 512), 512, 0, s2>>>(cnt, n);
    hist_kernel<<<cdiv(E, 512), 512, 0, s2>>>(dst, cnt, E);
    scan_block<<<nb, 512, 0, s2>>>(cnt, off, bsum, n);
    scan_sums<<<1, 512, 0, s2>>>(bsum, nb);
    scan_add<<<nb, 512, 0, s2>>>(off, bsum, cur, n);
    fill_kernel<<<cdiv(E, 512), 512, 0, s2>>>(src, dst, cur, esrc, E);
    cudaEventRecord(evJoin, s2);

    // ---- main: layer-0 tensor-core GEMM (fused in-kernel bf16 split for X) ----
    cvt_w_kernel<<<64, 256>>>(wl0, wr0, wth, wtl);
    mma_proj0<<<cdiv(n, 128), 256, SM_MMA>>>(emb, wth, wtl, ylr, n);

    // ---- join ----
    cudaStreamWaitEvent(0, evJoin, 0);

    gather_combine<64, true><<<cdiv(n * 32, TB), TB>>>(ylr, esrc, off, cnt, b0, xbuf, n);

    sgemm_proj_x2<64, 64, 128, 32, 4><<<cdiv(n, 128), 128, SM1>>>(xbuf, wl1, wr1, ylr, n);
    gather_combine<32, true><<<cdiv(n * 32, TB), TB>>>(ylr, esrc, off, cnt, b1, xbuf, n);

    proj_pernode<32, 16><<<cdiv(n, TB), TB>>>(xbuf, wl2, wr2, ylr, n);
    gather_combine<16, true><<<cdiv(n * 32, TB), TB>>>(ylr, esrc, off, cnt, b2, xbuf, n);

    proj3_pernode<<<cdiv(n, TB), TB>>>(xbuf, wl3, wr3, ylr, n);
    gather9<<<cdiv(n * 32, TB), TB>>>(ylr, esrc, off, cnt, b3, out, n);
}

// round 10
// speedup vs baseline: 1.0973x; 1.0973x over previous
#include <cuda_runtime.h>
#include <cuda_bf16.h>
#include <cstdint>

#define NMAX 100000
#define EMAX 600000

// Scratch (static device globals — allocation-free per harness rules)
__device__ __align__(16) float g_ylr[NMAX * 128];  // projected [y_l | y_r]
__device__ __align__(16) float g_x[NMAX * 64];     // layer activations
__device__ __align__(16) unsigned short g_wth[128 * 128];  // W0 hi bf16, n-major [n][k]
__device__ __align__(16) unsigned short g_wtl[128 * 128];  // W0 lo bf16, n-major [n][k]
__device__ int g_cnt[NMAX];
__device__ int g_off[NMAX];
__device__ int g_cur[NMAX];
__device__ int g_esrc[EMAX];
__device__ int g_bsum[512];

// ---------------------------------------------------------------------------
// cp.async + packed fma helpers (used by the f32x2 GEMM only)
// ---------------------------------------------------------------------------
__device__ __forceinline__ void cp_async16(uint32_t dst, const void* src, int src_bytes) {
    asm volatile("cp.async.cg.shared.global [%0], [%1], 16, %2;\n"
                 :: "r"(dst), "l"(src), "r"(src_bytes));
}
__device__ __forceinline__ void cp_commit() { asm volatile("cp.async.commit_group;\n"); }
template <int N>
__device__ __forceinline__ void cp_wait() { asm volatile("cp.async.wait_group %0;\n" :: "n"(N)); }

__device__ __forceinline__ void fma_x2(unsigned long long& acc, unsigned long long a2,
                                       unsigned long long b2) {
    asm("fma.rn.f32x2 %0, %1, %2, %0;" : "+l"(acc) : "l"(a2), "l"(b2));
}
__device__ __forceinline__ unsigned long long dup_f32(float a) {
    unsigned long long r;
    asm("mov.b64 %0, {%1, %1};" : "=l"(r) : "f"(a));
    return r;
}

// ---------------------------------------------------------------------------
// CSR build
// ---------------------------------------------------------------------------
__global__ void zero_int(int* __restrict__ p, int n) {
    int i = blockIdx.x * blockDim.x + threadIdx.x;
    if (i < n) p[i] = 0;
}

__global__ void hist_kernel(const int* __restrict__ dst, int* __restrict__ cnt, int E) {
    int i = blockIdx.x * blockDim.x + threadIdx.x;
    if (i < E) atomicAdd(&cnt[dst[i]], 1);
}

__device__ __forceinline__ int block_exscan_512(int v, int tid, int* warp_sums, int* total) {
    int lane = tid & 31, wid = tid >> 5;
    int inc = v;
#pragma unroll
    for (int st = 1; st < 32; st <<= 1) {
        int t = __shfl_up_sync(0xFFFFFFFFu, inc, st);
        if (lane >= st) inc += t;
    }
    if (lane == 31) warp_sums[wid] = inc;
    __syncthreads();
    if (wid == 0) {
        int ws = (lane < 16) ? warp_sums[lane] : 0;
#pragma unroll
        for (int st = 1; st < 16; st <<= 1) {
            int t = __shfl_up_sync(0xFFFFFFFFu, ws, st);
            if (lane >= st) ws += t;
        }
        if (lane < 16) warp_sums[lane] = ws;
    }
    __syncthreads();
    int base = (wid > 0) ? warp_sums[wid - 1] : 0;
    if (total) *total = warp_sums[15];
    return base + inc - v;
}

__global__ void scan_block(const int* __restrict__ cnt, int* __restrict__ off,
                           int* __restrict__ bsum, int n) {
    __shared__ int ws[16];
    int i = blockIdx.x * 512 + threadIdx.x;
    int v = (i < n) ? cnt[i] : 0;
    int total;
    int ex = block_exscan_512(v, threadIdx.x, ws, &total);
    if (i < n) off[i] = ex;
    if (threadIdx.x == 0) bsum[blockIdx.x] = total;
}

__global__ void scan_sums(int* __restrict__ bsum, int nb) {
    __shared__ int ws[16];
    int v = (threadIdx.x < nb) ? bsum[threadIdx.x] : 0;
    int ex = block_exscan_512(v, threadIdx.x, ws, nullptr);
    if (threadIdx.x < nb) bsum[threadIdx.x] = ex;
}

__global__ void scan_add(int* __restrict__ off, const int* __restrict__ bsum,
                         int* __restrict__ cur, int n) {
    int i = blockIdx.x * 512 + threadIdx.x;
    if (i < n) {
        int o = off[i] + bsum[blockIdx.x];
        off[i] = o;
        cur[i] = o;
    }
}

__global__ void fill_kernel(const int* __restrict__ src, const int* __restrict__ dst,
                            int* __restrict__ cur, int* __restrict__ esrc, int E) {
    int e = blockIdx.x * blockDim.x + threadIdx.x;
    if (e < E) {
        int p = atomicAdd(&cur[dst[e]], 1);
        esrc[p] = src[e];
    }
}

// ---------------------------------------------------------------------------
// W0 combined [k=128][n=128] -> transposed n-major bf16 hi/lo: wt[n*128 + k]
// ---------------------------------------------------------------------------
__global__ void cvt_w_kernel(const float* __restrict__ wl, const float* __restrict__ wr,
                             unsigned short* __restrict__ wth, unsigned short* __restrict__ wtl) {
    int i = blockIdx.x * blockDim.x + threadIdx.x;
    if (i >= 128 * 128) return;
    int nn = i >> 7, k = i & 127;
    float w = (nn < 64) ? wl[k * 64 + nn] : wr[k * 64 + (nn - 64)];
    __nv_bfloat16 h = __float2bfloat16(w);
    __nv_bfloat16 l = __float2bfloat16(w - __bfloat162float(h));
    wth[i] = *reinterpret_cast<unsigned short*>(&h);
    wtl[i] = *reinterpret_cast<unsigned short*>(&l);
}

// ---------------------------------------------------------------------------
// layer-0 tensor-core GEMM: ylr[n x 128] = X[n x 128] @ W[128 x 128]
// 3-term bf16 split, fp32 accum, mma.m16n8k16. X loaded fp32, split in-kernel.
// BM=64 (one m16 tile per warp; 4m x 2n warps), smem 104.4KB -> 2 blocks/SM
// so one block's staging overlaps the co-resident block's MMA compute.
// ---------------------------------------------------------------------------
__device__ __forceinline__ void mma16816(float* d, const unsigned* a,
                                         unsigned b0, unsigned b1) {
    asm volatile(
        "mma.sync.aligned.m16n8k16.row.col.f32.bf16.bf16.f32 "
        "{%0,%1,%2,%3}, {%4,%5,%6,%7}, {%8,%9}, {%0,%1,%2,%3};"
        : "+f"(d[0]), "+f"(d[1]), "+f"(d[2]), "+f"(d[3])
        : "r"(a[0]), "r"(a[1]), "r"(a[2]), "r"(a[3]), "r"(b0), "r"(b1));
}

__device__ __forceinline__ unsigned pack2_hi(float a, float b) {
    __nv_bfloat162 t;
    t.x = __float2bfloat16(a);
    t.y = __float2bfloat16(b);
    return *reinterpret_cast<unsigned*>(&t);
}

__global__ void __launch_bounds__(256, 2)
mma_proj0(const float* __restrict__ x, const unsigned short* __restrict__ wth,
          const unsigned short* __restrict__ wtl, float* __restrict__ ylr, int n) {
    constexpr int S = 136;  // smem row stride in halves (272B; 68 words == 4 mod 32)
    extern __shared__ __align__(16) unsigned short smu[];
    unsigned short* sXh = smu;              // [64][S]
    unsigned short* sXl = sXh + 64 * S;
    unsigned short* sWh = sXl + 64 * S;     // n-major [128][S]
    unsigned short* sWl = sWh + 128 * S;

    const int tid = threadIdx.x;
    const int lane = tid & 31;
    const int warp = tid >> 5;
    const int warpm = warp >> 1;   // 0..3: one m16 tile each (64 rows total)
    const int warpn = warp & 1;    // 0..1: 64 cols each
    const int nb = blockIdx.x * 64;
    const int mrem = n - nb;

    // stage X: 64 rows x 32 float4-chunks; fp32 -> bf16 hi/lo inline
    for (int idx = tid; idx < 64 * 32; idx += 256) {
        int r = idx >> 5, cc = (idx & 31) * 4;
        float4 v = make_float4(0.f, 0.f, 0.f, 0.f);
        if (r < mrem)
            v = *reinterpret_cast<const float4*>(&x[(size_t)(nb + r) * 128 + cc]);
        __nv_bfloat16 h0 = __float2bfloat16(v.x), h1 = __float2bfloat16(v.y);
        __nv_bfloat16 h2 = __float2bfloat16(v.z), h3 = __float2bfloat16(v.w);
        uint2 ph, pl;
        __nv_bfloat162 t;
        t.x = h0; t.y = h1; ph.x = *reinterpret_cast<unsigned*>(&t);
        t.x = h2; t.y = h3; ph.y = *reinterpret_cast<unsigned*>(&t);
        pl.x = pack2_hi(v.x - __bfloat162float(h0), v.y - __bfloat162float(h1));
        pl.y = pack2_hi(v.z - __bfloat162float(h2), v.w - __bfloat162float(h3));
        *reinterpret_cast<uint2*>(&sXh[r * S + cc]) = ph;
        *reinterpret_cast<uint2*>(&sXl[r * S + cc]) = pl;
    }
    // stage W: 128 n-rows x 16 uint4-chunks per array
    for (int idx = tid; idx < 128 * 16; idx += 256) {
        int r = idx >> 4, c = (idx & 15) * 8;
        *reinterpret_cast<uint4*>(&sWh[r * S + c]) =
            *reinterpret_cast<const uint4*>(&wth[r * 128 + c]);
        *reinterpret_cast<uint4*>(&sWl[r * S + c]) =
            *reinterpret_cast<const uint4*>(&wtl[r * 128 + c]);
    }
    __syncthreads();

    const int g = lane >> 2;        // 0..7
    const int t2 = (lane & 3) * 2;  // 0,2,4,6

    float acc[8][4];
#pragma unroll
    for (int nt = 0; nt < 8; ++nt)
#pragma unroll
        for (int t = 0; t < 4; ++t) acc[nt][t] = 0.f;

#pragma unroll
    for (int s = 0; s < 8; ++s) {
        const int k0 = s * 16;
        // A fragments (hi & lo), PTX m16n8k16 A map
        unsigned ah[4], al[4];
        {
            int r = warpm * 16 + g;
            ah[0] = *reinterpret_cast<const unsigned*>(&sXh[r * S + k0 + t2]);
            ah[1] = *reinterpret_cast<const unsigned*>(&sXh[(r + 8) * S + k0 + t2]);
            ah[2] = *reinterpret_cast<const unsigned*>(&sXh[r * S + k0 + t2 + 8]);
            ah[3] = *reinterpret_cast<const unsigned*>(&sXh[(r + 8) * S + k0 + t2 + 8]);
            al[0] = *reinterpret_cast<const unsigned*>(&sXl[r * S + k0 + t2]);
            al[1] = *reinterpret_cast<const unsigned*>(&sXl[(r + 8) * S + k0 + t2]);
            al[2] = *reinterpret_cast<const unsigned*>(&sXl[r * S + k0 + t2 + 8]);
            al[3] = *reinterpret_cast<const unsigned*>(&sXl[(r + 8) * S + k0 + t2 + 8]);
        }
#pragma unroll
        for (int nt = 0; nt < 8; ++nt) {
            int nn = warpn * 64 + nt * 8 + g;
            unsigned bh0 = *reinterpret_cast<const unsigned*>(&sWh[nn * S + k0 + t2]);
            unsigned bh1 = *reinterpret_cast<const unsigned*>(&sWh[nn * S + k0 + t2 + 8]);
            unsigned bl0 = *reinterpret_cast<const unsigned*>(&sWl[nn * S + k0 + t2]);
            unsigned bl1 = *reinterpret_cast<const unsigned*>(&sWl[nn * S + k0 + t2 + 8]);
            mma16816(acc[nt], ah, bh0, bh1);  // Xh*Wh
            mma16816(acc[nt], al, bh0, bh1);  // Xl*Wh
            mma16816(acc[nt], ah, bl0, bl1);  // Xh*Wl
        }
    }

    // epilogue: D map — c0,c1: (g, t2..t2+1); c2,c3: (g+8, ..)
#pragma unroll
    for (int nt = 0; nt < 8; ++nt) {
        int col = warpn * 64 + nt * 8 + t2;
        int node0 = nb + warpm * 16 + g;
        int node1 = node0 + 8;
        if (node0 < n) {
            float2 v = make_float2(acc[nt][0], acc[nt][1]);
            *reinterpret_cast<float2*>(&ylr[(size_t)node0 * 128 + col]) = v;
        }
        if (node1 < n) {
            float2 v = make_float2(acc[nt][2], acc[nt][3]);
            *reinterpret_cast<float2*>(&ylr[(size_t)node1 * 128 + col]) = v;
        }
    }
}

// ---------------------------------------------------------------------------
// projection GEMM (packed f32x2) — layer 1
// ---------------------------------------------------------------------------
template <int K, int NC, int BM, int BK, int MINBLK>
__global__ void __launch_bounds__((BM / 8) * (NC / 8), MINBLK)
sgemm_proj_x2(const float* __restrict__ x, const float* __restrict__ wl,
              const float* __restrict__ wr, float* __restrict__ ylr, int n) {
    constexpr int TM = 8;
    constexpr int PAD = 4;
    constexpr int F = NC / 2;
    constexpr int NTH = (BM / TM) * (NC / 8);
    constexpr int KT = K / BK;
    constexpr int XS = BK + PAD;

    extern __shared__ float smf[];
    float* sX = smf;
    float* sB = smf + 2 * BM * XS;

    const int tid = threadIdx.x;
    const int nb = blockIdx.x * BM;
    const int mrem = n - nb;

    auto load_tile = [&](int kb, int buf) {
        const int k0 = kb * BK;
        float* sXb = sX + buf * BM * XS;
        float* sBb = sB + buf * BK * NC;
        for (int idx = tid; idx < BM * BK / 4; idx += NTH) {
            int m = idx / (BK / 4);
            int kc = idx % (BK / 4);
            uint32_t dst = (uint32_t)__cvta_generic_to_shared(&sXb[m * XS + kc * 4]);
            int mm = (m < mrem) ? m : 0;
            const float* src = x + (size_t)(nb + mm) * K + k0 + kc * 4;
            cp_async16(dst, src, (m < mrem) ? 16 : 0);
        }
        for (int idx = tid; idx < BK * NC / 4; idx += NTH) {
            int kr = idx / (NC / 4);
            int j = (idx % (NC / 4)) * 4;
            const float* src = (j < F) ? (wl + (size_t)(kr + k0) * F + j)
                                       : (wr + (size_t)(kr + k0) * F + (j - F));
            uint32_t dst = (uint32_t)__cvta_generic_to_shared(&sBb[kr * NC + j]);
            cp_async16(dst, src, 16);
        }
    };

    load_tile(0, 0);
    cp_commit();

    constexpr int CG = NC / 8;
    const int tj = tid % CG;
    const int ti = tid / CG;
    const int m0 = ti * TM;
    const int jA = tj * 4;
    const int jB = jA + F;

    unsigned long long acc[TM][4];
#pragma unroll
    for (int i = 0; i < TM; ++i)
#pragma unroll
        for (int t = 0; t < 4; ++t) acc[i][t] = 0ull;

    for (int kb = 0; kb < KT; ++kb) {
        if (kb + 1 < KT) {
            load_tile(kb + 1, (kb + 1) & 1);
            cp_commit();
            cp_wait<1>();
        } else {
            cp_wait<0>();
        }
        __syncthreads();

        const float* bx = sX + (kb & 1) * BM * XS;
        const float* bb = sB + (kb & 1) * BK * NC;
#pragma unroll
        for (int k = 0; k < BK; ++k) {
            ulonglong2 bp0 = *reinterpret_cast<const ulonglong2*>(&bb[k * NC + jA]);
            ulonglong2 bp1 = *reinterpret_cast<const ulonglong2*>(&bb[k * NC + jB]);
#pragma unroll
            for (int i = 0; i < TM; ++i) {
                unsigned long long a2 = dup_f32(bx[(m0 + i) * XS + k]);
                fma_x2(acc[i][0], a2, bp0.x);
                fma_x2(acc[i][1], a2, bp0.y);
                fma_x2(acc[i][2], a2, bp1.x);
                fma_x2(acc[i][3], a2, bp1.y);
            }
        }
        __syncthreads();
    }

#pragma unroll
    for (int i = 0; i < TM; ++i) {
        int node = nb + m0 + i;
        if (node < n) {
            ulonglong2 v0, v1;
            v0.x = acc[i][0]; v0.y = acc[i][1];
            v1.x = acc[i][2]; v1.y = acc[i][3];
            *reinterpret_cast<ulonglong2*>(&ylr[(size_t)node * NC + jA]) = v0;
            *reinterpret_cast<ulonglong2*>(&ylr[(size_t)node * NC + jB]) = v1;
        }
    }
}

// ---------------------------------------------------------------------------
// per-node projection for small layers
// ---------------------------------------------------------------------------
template <int K, int F>
__global__ void proj_pernode(const float* __restrict__ x, const float* __restrict__ wl,
                             const float* __restrict__ wr, float* __restrict__ ylr, int n) {
    constexpr int NC = 2 * F;
    __shared__ float sB[K * NC];
    for (int i = threadIdx.x; i < K * NC; i += blockDim.x) {
        int k = i / NC, j = i % NC;
        sB[i] = (j < F) ? wl[k * F + j] : wr[k * F + (j - F)];
    }
    __syncthreads();

    int node = blockIdx.x * blockDim.x + threadIdx.x;
    if (node >= n) return;

    float xv[K];
    const float4* xr = reinterpret_cast<const float4*>(x + (size_t)node * K);
#pragma unroll
    for (int c = 0; c < K / 4; ++c) {
        float4 v = xr[c];
        xv[c * 4 + 0] = v.x; xv[c * 4 + 1] = v.y; xv[c * 4 + 2] = v.z; xv[c * 4 + 3] = v.w;
    }
    float acc[NC];
#pragma unroll
    for (int j = 0; j < NC; ++j) acc[j] = 0.f;
#pragma unroll
    for (int k = 0; k < K; ++k) {
        float a = xv[k];
#pragma unroll
        for (int j = 0; j < NC; ++j) acc[j] = fmaf(a, sB[k * NC + j], acc[j]);
    }
    float4* o = reinterpret_cast<float4*>(ylr + (size_t)node * NC);
#pragma unroll
    for (int c = 0; c < NC / 4; ++c)
        o[c] = make_float4(acc[c * 4], acc[c * 4 + 1], acc[c * 4 + 2], acc[c * 4 + 3]);
}

__global__ void proj3_pernode(const float* __restrict__ x, const float* __restrict__ wl,
                              const float* __restrict__ wr, float* __restrict__ ylr3, int n) {
    __shared__ float swl[16 * 9];
    __shared__ float swr[16 * 9];
    for (int i = threadIdx.x; i < 144; i += blockDim.x) {
        swl[i] = wl[i];
        swr[i] = wr[i];
    }
    __syncthreads();

    int node = blockIdx.x * blockDim.x + threadIdx.x;
    if (node >= n) return;

    float xv[16];
    const float4* xr = reinterpret_cast<const float4*>(x + (size_t)node * 16);
#pragma unroll
    for (int c = 0; c < 4; ++c) {
        float4 v = xr[c];
        xv[c * 4 + 0] = v.x; xv[c * 4 + 1] = v.y; xv[c * 4 + 2] = v.z; xv[c * 4 + 3] = v.w;
    }
    float al[9], ar[9];
#pragma unroll
    for (int j = 0; j < 9; ++j) { al[j] = 0.f; ar[j] = 0.f; }
#pragma unroll
    for (int k = 0; k < 16; ++k) {
        float a = xv[k];
#pragma unroll
        for (int j = 0; j < 9; ++j) {
            al[j] = fmaf(a, swl[k * 9 + j], al[j]);
            ar[j] = fmaf(a, swr[k * 9 + j], ar[j]);
        }
    }
    float4* o = reinterpret_cast<float4*>(ylr3 + (size_t)node * 32);
    o[0] = make_float4(al[0], al[1], al[2], al[3]);
    o[1] = make_float4(al[4], al[5], al[6], al[7]);
    o[2] = make_float4(al[8], 0.f, 0.f, 0.f);
    o[3] = make_float4(0.f, 0.f, 0.f, 0.f);
    o[4] = make_float4(ar[0], ar[1], ar[2], ar[3]);
    o[5] = make_float4(ar[4], ar[5], ar[6], ar[7]);
    ylr3[(size_t)node * 32 + 24] = ar[8];
}

// ---------------------------------------------------------------------------
// gather + combine (fused): warp per node.
// ---------------------------------------------------------------------------
template <int F, bool RELU>
__global__ void gather_combine(const float* __restrict__ ylr, const int* __restrict__ esrc,
                               const int* __restrict__ off, const int* __restrict__ cnt,
                               const float* __restrict__ bias, float* __restrict__ out, int n) {
    constexpr int CH = F / 4;
    constexpr int EPW = 32 / CH;
    int w = (blockIdx.x * blockDim.x + threadIdx.x) >> 5;
    if (w >= n) return;
    int lane = threadIdx.x & 31;
    int c = lane % CH, g = lane / CH;
    int start = off[w], deg = cnt[w];

    float4 acc = make_float4(0.f, 0.f, 0.f, 0.f);
    const float4* y4 = reinterpret_cast<const float4*>(ylr);
    for (int j = g; j < deg; j += EPW) {
        int s = __ldg(esrc + start + j);
        float4 v = y4[(size_t)s * (F / 2) + c];
        acc.x += v.x; acc.y += v.y; acc.z += v.z; acc.w += v.w;
    }
#pragma unroll
    for (int st = 16; st >= CH; st >>= 1) {
        acc.x += __shfl_xor_sync(0xFFFFFFFFu, acc.x, st);
        acc.y += __shfl_xor_sync(0xFFFFFFFFu, acc.y, st);
        acc.z += __shfl_xor_sync(0xFFFFFFFFu, acc.z, st);
        acc.w += __shfl_xor_sync(0xFFFFFFFFu, acc.w, st);
    }
    if (lane < CH) {
        float iv = __frcp_rn(fmaxf((float)deg, 1.0f));
        float4 r = y4[(size_t)w * (F / 2) + (F / 4) + c];
        float4 b = reinterpret_cast<const float4*>(bias)[c];
        float4 v;
        v.x = fmaf(acc.x, iv, r.x) + b.x;
        v.y = fmaf(acc.y, iv, r.y) + b.y;
        v.z = fmaf(acc.z, iv, r.z) + b.z;
        v.w = fmaf(acc.w, iv, r.w) + b.w;
        if (RELU) {
            v.x = fmaxf(v.x, 0.f); v.y = fmaxf(v.y, 0.f);
            v.z = fmaxf(v.z, 0.f); v.w = fmaxf(v.w, 0.f);
        }
        reinterpret_cast<float4*>(out)[(size_t)w * CH + c] = v;
    }
}

__global__ void gather9(const float* __restrict__ ylr3, const int* __restrict__ esrc,
                        const int* __restrict__ off, const int* __restrict__ cnt,
                        const float* __restrict__ bias, float* __restrict__ out, int n) {
    int w = (blockIdx.x * blockDim.x + threadIdx.x) >> 5;
    if (w >= n) return;
    int lane = threadIdx.x & 31;
    int c = lane % 4, g = lane / 4;
    int start = off[w], deg = cnt[w];

    float4 acc = make_float4(0.f, 0.f, 0.f, 0.f);
    const float4* y4 = reinterpret_cast<const float4*>(ylr3);
    for (int j = g; j < deg; j += 8) {
        int s = __ldg(esrc + start + j);
        float4 v = y4[(size_t)s * 8 + c];
        acc.x += v.x; acc.y += v.y; acc.z += v.z; acc.w += v.w;
    }
#pragma unroll
    for (int st = 16; st >= 4; st >>= 1) {
        acc.x += __shfl_xor_sync(0xFFFFFFFFu, acc.x, st);
        acc.y += __shfl_xor_sync(0xFFFFFFFFu, acc.y, st);
        acc.z += __shfl_xor_sync(0xFFFFFFFFu, acc.z, st);
        acc.w += __shfl_xor_sync(0xFFFFFFFFu, acc.w, st);
    }
    if (lane < 4) {
        float iv = __frcp_rn(fmaxf((float)deg, 1.0f));
        float a[4] = {acc.x, acc.y, acc.z, acc.w};
#pragma unroll
        for (int t = 0; t < 4; ++t) {
            int j = c * 4 + t;
            if (j < 9) {
                float yr = ylr3[(size_t)w * 32 + 16 + j];
                out[(size_t)w * 9 + j] = fmaf(a[t], iv, yr + __ldg(bias + j));
            }
        }
    }
}

// ---------------------------------------------------------------------------
// launch
// ---------------------------------------------------------------------------
extern "C" void kernel_launch(void* const* d_in, const int* in_sizes, int n_in,
                              void* d_out, int out_size) {
    const float* emb = (const float*)d_in[0];
    const int* ei = (const int*)d_in[1];
    const float* wl0 = (const float*)d_in[3];
    const float* wr0 = (const float*)d_in[4];
    const float* b0  = (const float*)d_in[5];
    const float* wl1 = (const float*)d_in[6];
    const float* wr1 = (const float*)d_in[7];
    const float* b1  = (const float*)d_in[8];
    const float* wl2 = (const float*)d_in[9];
    const float* wr2 = (const float*)d_in[10];
    const float* b2  = (const float*)d_in[11];
    const float* wl3 = (const float*)d_in[12];
    const float* wr3 = (const float*)d_in[13];
    const float* b3  = (const float*)d_in[14];
    float* out = (float*)d_out;

    const int n = in_sizes[0] / 128;
    const int E = in_sizes[1] / 2;
    const int* src = ei;
    const int* dst = ei + E;

    float *ylr, *xbuf;
    unsigned short *wth, *wtl;
    int *cnt, *off, *cur, *esrc, *bsum;
    cudaGetSymbolAddress((void**)&ylr, g_ylr);
    cudaGetSymbolAddress((void**)&xbuf, g_x);
    cudaGetSymbolAddress((void**)&wth, g_wth);
    cudaGetSymbolAddress((void**)&wtl, g_wtl);
    cudaGetSymbolAddress((void**)&cnt, g_cnt);
    cudaGetSymbolAddress((void**)&off, g_off);
    cudaGetSymbolAddress((void**)&cur, g_cur);
    cudaGetSymbolAddress((void**)&esrc, g_esrc);
    cudaGetSymbolAddress((void**)&bsum, g_bsum);

    auto cdiv = [](int a, int b) { return (a + b - 1) / b; };
    const int TB = 256;
    const int nb = cdiv(n, 512);

    const int SM_MMA = (2 * 64 * 136 + 2 * 128 * 136) * 2;  // 104448
    const int SM1 = (2 * 128 * 36 + 2 * 32 * 64) * 4;       // 53248
    cudaFuncSetAttribute((const void*)mma_proj0,
                         cudaFuncAttributeMaxDynamicSharedMemorySize, SM_MMA);
    cudaFuncSetAttribute((const void*)sgemm_proj_x2<64, 64, 128, 32, 4>,
                         cudaFuncAttributeMaxDynamicSharedMemorySize, SM1);

    static cudaStream_t s2 = nullptr;
    static cudaEvent_t evFork = nullptr, evJoin = nullptr;
    if (!s2) {
        cudaStreamCreateWithFlags(&s2, cudaStreamNonBlocking);
        cudaEventCreateWithFlags(&evFork, cudaEventDisableTiming);
        cudaEventCreateWithFlags(&evJoin, cudaEventDisableTiming);
    }

    // ---- fork: CSR build on s2 ----
    cudaEventRecord(evFork, 0);
    cudaStreamWaitEvent(s2, evFork, 0);

    zero_int<<<cdiv(n, 512), 512, 0, s2>>>(cnt, n);
    hist_kernel<<<cdiv(E, 512), 512, 0, s2>>>(dst, cnt, E);
    scan_block<<<nb, 512, 0, s2>>>(cnt, off, bsum, n);
    scan_sums<<<1, 512, 0, s2>>>(bsum, nb);
    scan_add<<<nb, 512, 0, s2>>>(off, bsum, cur, n);
    fill_kernel<<<cdiv(E, 512), 512, 0, s2>>>(src, dst, cur, esrc, E);
    cudaEventRecord(evJoin, s2);

    // ---- main: layer-0 tensor-core GEMM (fused in-kernel bf16 split for X) ----
    cvt_w_kernel<<<64, 256>>>(wl0, wr0, wth, wtl);
    mma_proj0<<<cdiv(n, 64), 256, SM_MMA>>>(emb, wth, wtl, ylr, n);

    // ---- join ----
    cudaStreamWaitEvent(0, evJoin, 0);

    gather_combine<64, true><<<cdiv(n * 32, TB), TB>>>(ylr, esrc, off, cnt, b0, xbuf, n);

    sgemm_proj_x2<64, 64, 128, 32, 4><<<cdiv(n, 128), 128, SM1>>>(xbuf, wl1, wr1, ylr, n);
    gather_combine<32, true><<<cdiv(n * 32, TB), TB>>>(ylr, esrc, off, cnt, b1, xbuf, n);

    proj_pernode<32, 16><<<cdiv(n, TB), TB>>>(xbuf, wl2, wr2, ylr, n);
    gather_combine<16, true><<<cdiv(n * 32, TB), TB>>>(ylr, esrc, off, cnt, b2, xbuf, n);

    proj3_pernode<<<cdiv(n, TB), TB>>>(xbuf, wl3, wr3, ylr, n);
    gather9<<<cdiv(n * 32, TB), TB>>>(ylr, esrc, off, cnt, b3, out, n);
}

// round 11
// speedup vs baseline: 1.2029x; 1.0963x over previous
#include <cuda_runtime.h>
#include <cuda_bf16.h>
#include <cstdint>

#define NMAX 100000
#define EMAX 600000

// Scratch (static device globals — allocation-free per harness rules)
__device__ __align__(16) float g_ylr[NMAX * 128];  // projected [y_l | y_r]
__device__ __align__(16) float g_x[NMAX * 64];     // layer activations
__device__ __align__(16) unsigned short g_wth[128 * 128];  // W0 hi bf16, n-major [n][k]
__device__ __align__(16) unsigned short g_wtl[128 * 128];  // W0 lo bf16, n-major [n][k]
__device__ int g_cnt[NMAX];
__device__ int g_off[NMAX];
__device__ int g_cur[NMAX];
__device__ int g_esrc[EMAX];
__device__ int g_bsum[512];

// ---------------------------------------------------------------------------
// cp.async + packed fma helpers (used by the f32x2 GEMM only)
// ---------------------------------------------------------------------------
__device__ __forceinline__ void cp_async16(uint32_t dst, const void* src, int src_bytes) {
    asm volatile("cp.async.cg.shared.global [%0], [%1], 16, %2;\n"
                 :: "r"(dst), "l"(src), "r"(src_bytes));
}
__device__ __forceinline__ void cp_commit() { asm volatile("cp.async.commit_group;\n"); }
template <int N>
__device__ __forceinline__ void cp_wait() { asm volatile("cp.async.wait_group %0;\n" :: "n"(N)); }

__device__ __forceinline__ void fma_x2(unsigned long long& acc, unsigned long long a2,
                                       unsigned long long b2) {
    asm("fma.rn.f32x2 %0, %1, %2, %0;" : "+l"(acc) : "l"(a2), "l"(b2));
}
__device__ __forceinline__ unsigned long long dup_f32(float a) {
    unsigned long long r;
    asm("mov.b64 %0, {%1, %1};" : "=l"(r) : "f"(a));
    return r;
}

// ---------------------------------------------------------------------------
// CSR build
// ---------------------------------------------------------------------------
__global__ void zero_int(int* __restrict__ p, int n) {
    int i = blockIdx.x * blockDim.x + threadIdx.x;
    if (i < n) p[i] = 0;
}

__global__ void hist_kernel(const int* __restrict__ dst, int* __restrict__ cnt, int E) {
    int i = blockIdx.x * blockDim.x + threadIdx.x;
    if (i < E) atomicAdd(&cnt[dst[i]], 1);
}

__device__ __forceinline__ int block_exscan_512(int v, int tid, int* warp_sums, int* total) {
    int lane = tid & 31, wid = tid >> 5;
    int inc = v;
#pragma unroll
    for (int st = 1; st < 32; st <<= 1) {
        int t = __shfl_up_sync(0xFFFFFFFFu, inc, st);
        if (lane >= st) inc += t;
    }
    if (lane == 31) warp_sums[wid] = inc;
    __syncthreads();
    if (wid == 0) {
        int ws = (lane < 16) ? warp_sums[lane] : 0;
#pragma unroll
        for (int st = 1; st < 16; st <<= 1) {
            int t = __shfl_up_sync(0xFFFFFFFFu, ws, st);
            if (lane >= st) ws += t;
        }
        if (lane < 16) warp_sums[lane] = ws;
    }
    __syncthreads();
    int base = (wid > 0) ? warp_sums[wid - 1] : 0;
    if (total) *total = warp_sums[15];
    return base + inc - v;
}

__global__ void scan_block(const int* __restrict__ cnt, int* __restrict__ off,
                           int* __restrict__ bsum, int n) {
    __shared__ int ws[16];
    int i = blockIdx.x * 512 + threadIdx.x;
    int v = (i < n) ? cnt[i] : 0;
    int total;
    int ex = block_exscan_512(v, threadIdx.x, ws, &total);
    if (i < n) off[i] = ex;
    if (threadIdx.x == 0) bsum[blockIdx.x] = total;
}

__global__ void scan_sums(int* __restrict__ bsum, int nb) {
    __shared__ int ws[16];
    int v = (threadIdx.x < nb) ? bsum[threadIdx.x] : 0;
    int ex = block_exscan_512(v, threadIdx.x, ws, nullptr);
    if (threadIdx.x < nb) bsum[threadIdx.x] = ex;
}

__global__ void scan_add(int* __restrict__ off, const int* __restrict__ bsum,
                         int* __restrict__ cur, int n) {
    int i = blockIdx.x * 512 + threadIdx.x;
    if (i < n) {
        int o = off[i] + bsum[blockIdx.x];
        off[i] = o;
        cur[i] = o;
    }
}

__global__ void fill_kernel(const int* __restrict__ src, const int* __restrict__ dst,
                            int* __restrict__ cur, int* __restrict__ esrc, int E) {
    int e = blockIdx.x * blockDim.x + threadIdx.x;
    if (e < E) {
        int p = atomicAdd(&cur[dst[e]], 1);
        esrc[p] = src[e];
    }
}

// ---------------------------------------------------------------------------
// W0 combined [k=128][n=128] -> transposed n-major bf16 hi/lo: wt[n*128 + k]
// ---------------------------------------------------------------------------
__global__ void cvt_w_kernel(const float* __restrict__ wl, const float* __restrict__ wr,
                             unsigned short* __restrict__ wth, unsigned short* __restrict__ wtl) {
    int i = blockIdx.x * blockDim.x + threadIdx.x;
    if (i >= 128 * 128) return;
    int nn = i >> 7, k = i & 127;
    float w = (nn < 64) ? wl[k * 64 + nn] : wr[k * 64 + (nn - 64)];
    __nv_bfloat16 h = __float2bfloat16(w);
    __nv_bfloat16 l = __float2bfloat16(w - __bfloat162float(h));
    wth[i] = *reinterpret_cast<unsigned short*>(&h);
    wtl[i] = *reinterpret_cast<unsigned short*>(&l);
}

// ---------------------------------------------------------------------------
// layer-0 tensor-core GEMM (persistent): ylr[n x 128] = X[n x 128] @ W[128 x 128]
// 3-term bf16 split, fp32 accum, mma.m16n8k16. BM=64 per tile; W staged ONCE
// per persistent block; next tile's fp32 X prefetched in registers so its LDG
// latency hides under the current tile's MMA compute. 2 blocks/SM.
// ---------------------------------------------------------------------------
__device__ __forceinline__ void mma16816(float* d, const unsigned* a,
                                         unsigned b0, unsigned b1) {
    asm volatile(
        "mma.sync.aligned.m16n8k16.row.col.f32.bf16.bf16.f32 "
        "{%0,%1,%2,%3}, {%4,%5,%6,%7}, {%8,%9}, {%0,%1,%2,%3};"
        : "+f"(d[0]), "+f"(d[1]), "+f"(d[2]), "+f"(d[3])
        : "r"(a[0]), "r"(a[1]), "r"(a[2]), "r"(a[3]), "r"(b0), "r"(b1));
}

__device__ __forceinline__ unsigned pack2_hi(float a, float b) {
    __nv_bfloat162 t;
    t.x = __float2bfloat16(a);
    t.y = __float2bfloat16(b);
    return *reinterpret_cast<unsigned*>(&t);
}

__global__ void __launch_bounds__(256, 2)
mma_proj0(const float* __restrict__ x, const unsigned short* __restrict__ wth,
          const unsigned short* __restrict__ wtl, float* __restrict__ ylr,
          int n, int ntiles) {
    constexpr int S = 136;  // smem row stride in halves (272B; 68 words == 4 mod 32)
    extern __shared__ __align__(16) unsigned short smu[];
    unsigned short* sXh = smu;              // [64][S]
    unsigned short* sXl = sXh + 64 * S;
    unsigned short* sWh = sXl + 64 * S;     // n-major [128][S]
    unsigned short* sWl = sWh + 128 * S;

    const int tid = threadIdx.x;
    const int lane = tid & 31;
    const int warp = tid >> 5;
    const int warpm = warp >> 1;   // 0..3: one m16 tile each (64 rows)
    const int warpn = warp & 1;    // 0..1: 64 cols each
    const int g = lane >> 2;       // 0..7
    const int t2 = (lane & 3) * 2; // 0,2,4,6

    // stage W once per persistent block
    for (int idx = tid; idx < 128 * 16; idx += 256) {
        int r = idx >> 4, c = (idx & 15) * 8;
        *reinterpret_cast<uint4*>(&sWh[r * S + c]) =
            *reinterpret_cast<const uint4*>(&wth[r * 128 + c]);
        *reinterpret_cast<uint4*>(&sWl[r * S + c]) =
            *reinterpret_cast<const uint4*>(&wtl[r * 128 + c]);
    }

    // per-thread X chunk coordinates (8 float4s cover the 64x128 tile)
    // idx = tid + i*256; r = idx>>5; cc = (idx&31)*4
    float4 xf[8];
    auto load_x = [&](int tile) {
        const int nb = tile * 64;
        const int mrem = n - nb;
#pragma unroll
        for (int i = 0; i < 8; ++i) {
            int idx = tid + i * 256;
            int r = idx >> 5, cc = (idx & 31) * 4;
            float4 v = make_float4(0.f, 0.f, 0.f, 0.f);
            if (r < mrem)
                v = *reinterpret_cast<const float4*>(&x[(size_t)(nb + r) * 128 + cc]);
            xf[i] = v;
        }
    };

    int tile = blockIdx.x;
    if (tile < ntiles) load_x(tile);

    while (tile < ntiles) {
        // convert current tile's registers -> smem (bf16 hi/lo)
#pragma unroll
        for (int i = 0; i < 8; ++i) {
            int idx = tid + i * 256;
            int r = idx >> 5, cc = (idx & 31) * 4;
            float4 v = xf[i];
            __nv_bfloat16 h0 = __float2bfloat16(v.x), h1 = __float2bfloat16(v.y);
            __nv_bfloat16 h2 = __float2bfloat16(v.z), h3 = __float2bfloat16(v.w);
            uint2 ph, pl;
            __nv_bfloat162 t;
            t.x = h0; t.y = h1; ph.x = *reinterpret_cast<unsigned*>(&t);
            t.x = h2; t.y = h3; ph.y = *reinterpret_cast<unsigned*>(&t);
            pl.x = pack2_hi(v.x - __bfloat162float(h0), v.y - __bfloat162float(h1));
            pl.y = pack2_hi(v.z - __bfloat162float(h2), v.w - __bfloat162float(h3));
            *reinterpret_cast<uint2*>(&sXh[r * S + cc]) = ph;
            *reinterpret_cast<uint2*>(&sXl[r * S + cc]) = pl;
        }
        __syncthreads();

        const int nb = tile * 64;
        const int next = tile + gridDim.x;
        if (next < ntiles) load_x(next);  // LDG latency hides under MMA below

        float acc[8][4];
#pragma unroll
        for (int nt = 0; nt < 8; ++nt)
#pragma unroll
            for (int t = 0; t < 4; ++t) acc[nt][t] = 0.f;

#pragma unroll
        for (int s = 0; s < 8; ++s) {
            const int k0 = s * 16;
            unsigned ah[4], al[4];
            {
                int r = warpm * 16 + g;
                ah[0] = *reinterpret_cast<const unsigned*>(&sXh[r * S + k0 + t2]);
                ah[1] = *reinterpret_cast<const unsigned*>(&sXh[(r + 8) * S + k0 + t2]);
                ah[2] = *reinterpret_cast<const unsigned*>(&sXh[r * S + k0 + t2 + 8]);
                ah[3] = *reinterpret_cast<const unsigned*>(&sXh[(r + 8) * S + k0 + t2 + 8]);
                al[0] = *reinterpret_cast<const unsigned*>(&sXl[r * S + k0 + t2]);
                al[1] = *reinterpret_cast<const unsigned*>(&sXl[(r + 8) * S + k0 + t2]);
                al[2] = *reinterpret_cast<const unsigned*>(&sXl[r * S + k0 + t2 + 8]);
                al[3] = *reinterpret_cast<const unsigned*>(&sXl[(r + 8) * S + k0 + t2 + 8]);
            }
#pragma unroll
            for (int nt = 0; nt < 8; ++nt) {
                int nn = warpn * 64 + nt * 8 + g;
                unsigned bh0 = *reinterpret_cast<const unsigned*>(&sWh[nn * S + k0 + t2]);
                unsigned bh1 = *reinterpret_cast<const unsigned*>(&sWh[nn * S + k0 + t2 + 8]);
                unsigned bl0 = *reinterpret_cast<const unsigned*>(&sWl[nn * S + k0 + t2]);
                unsigned bl1 = *reinterpret_cast<const unsigned*>(&sWl[nn * S + k0 + t2 + 8]);
                mma16816(acc[nt], ah, bh0, bh1);  // Xh*Wh
                mma16816(acc[nt], al, bh0, bh1);  // Xl*Wh
                mma16816(acc[nt], ah, bl0, bl1);  // Xh*Wl
            }
        }

        // epilogue: D map — c0,c1: (g, t2..t2+1); c2,c3: (g+8, ..)
#pragma unroll
        for (int nt = 0; nt < 8; ++nt) {
            int col = warpn * 64 + nt * 8 + t2;
            int node0 = nb + warpm * 16 + g;
            int node1 = node0 + 8;
            if (node0 < n) {
                float2 v = make_float2(acc[nt][0], acc[nt][1]);
                *reinterpret_cast<float2*>(&ylr[(size_t)node0 * 128 + col]) = v;
            }
            if (node1 < n) {
                float2 v = make_float2(acc[nt][2], acc[nt][3]);
                *reinterpret_cast<float2*>(&ylr[(size_t)node1 * 128 + col]) = v;
            }
        }

        __syncthreads();  // before overwriting sXh/sXl next iteration
        tile = next;
    }
}

// ---------------------------------------------------------------------------
// projection GEMM (packed f32x2) — layer 1
// ---------------------------------------------------------------------------
template <int K, int NC, int BM, int BK, int MINBLK>
__global__ void __launch_bounds__((BM / 8) * (NC / 8), MINBLK)
sgemm_proj_x2(const float* __restrict__ x, const float* __restrict__ wl,
              const float* __restrict__ wr, float* __restrict__ ylr, int n) {
    constexpr int TM = 8;
    constexpr int PAD = 4;
    constexpr int F = NC / 2;
    constexpr int NTH = (BM / TM) * (NC / 8);
    constexpr int KT = K / BK;
    constexpr int XS = BK + PAD;

    extern __shared__ float smf[];
    float* sX = smf;
    float* sB = smf + 2 * BM * XS;

    const int tid = threadIdx.x;
    const int nb = blockIdx.x * BM;
    const int mrem = n - nb;

    auto load_tile = [&](int kb, int buf) {
        const int k0 = kb * BK;
        float* sXb = sX + buf * BM * XS;
        float* sBb = sB + buf * BK * NC;
        for (int idx = tid; idx < BM * BK / 4; idx += NTH) {
            int m = idx / (BK / 4);
            int kc = idx % (BK / 4);
            uint32_t dst = (uint32_t)__cvta_generic_to_shared(&sXb[m * XS + kc * 4]);
            int mm = (m < mrem) ? m : 0;
            const float* src = x + (size_t)(nb + mm) * K + k0 + kc * 4;
            cp_async16(dst, src, (m < mrem) ? 16 : 0);
        }
        for (int idx = tid; idx < BK * NC / 4; idx += NTH) {
            int kr = idx / (NC / 4);
            int j = (idx % (NC / 4)) * 4;
            const float* src = (j < F) ? (wl + (size_t)(kr + k0) * F + j)
                                       : (wr + (size_t)(kr + k0) * F + (j - F));
            uint32_t dst = (uint32_t)__cvta_generic_to_shared(&sBb[kr * NC + j]);
            cp_async16(dst, src, 16);
        }
    };

    load_tile(0, 0);
    cp_commit();

    constexpr int CG = NC / 8;
    const int tj = tid % CG;
    const int ti = tid / CG;
    const int m0 = ti * TM;
    const int jA = tj * 4;
    const int jB = jA + F;

    unsigned long long acc[TM][4];
#pragma unroll
    for (int i = 0; i < TM; ++i)
#pragma unroll
        for (int t = 0; t < 4; ++t) acc[i][t] = 0ull;

    for (int kb = 0; kb < KT; ++kb) {
        if (kb + 1 < KT) {
            load_tile(kb + 1, (kb + 1) & 1);
            cp_commit();
            cp_wait<1>();
        } else {
            cp_wait<0>();
        }
        __syncthreads();

        const float* bx = sX + (kb & 1) * BM * XS;
        const float* bb = sB + (kb & 1) * BK * NC;
#pragma unroll
        for (int k = 0; k < BK; ++k) {
            ulonglong2 bp0 = *reinterpret_cast<const ulonglong2*>(&bb[k * NC + jA]);
            ulonglong2 bp1 = *reinterpret_cast<const ulonglong2*>(&bb[k * NC + jB]);
#pragma unroll
            for (int i = 0; i < TM; ++i) {
                unsigned long long a2 = dup_f32(bx[(m0 + i) * XS + k]);
                fma_x2(acc[i][0], a2, bp0.x);
                fma_x2(acc[i][1], a2, bp0.y);
                fma_x2(acc[i][2], a2, bp1.x);
                fma_x2(acc[i][3], a2, bp1.y);
            }
        }
        __syncthreads();
    }

#pragma unroll
    for (int i = 0; i < TM; ++i) {
        int node = nb + m0 + i;
        if (node < n) {
            ulonglong2 v0, v1;
            v0.x = acc[i][0]; v0.y = acc[i][1];
            v1.x = acc[i][2]; v1.y = acc[i][3];
            *reinterpret_cast<ulonglong2*>(&ylr[(size_t)node * NC + jA]) = v0;
            *reinterpret_cast<ulonglong2*>(&ylr[(size_t)node * NC + jB]) = v1;
        }
    }
}

// ---------------------------------------------------------------------------
// per-node projection for small layers
// ---------------------------------------------------------------------------
template <int K, int F>
__global__ void proj_pernode(const float* __restrict__ x, const float* __restrict__ wl,
                             const float* __restrict__ wr, float* __restrict__ ylr, int n) {
    constexpr int NC = 2 * F;
    __shared__ float sB[K * NC];
    for (int i = threadIdx.x; i < K * NC; i += blockDim.x) {
        int k = i / NC, j = i % NC;
        sB[i] = (j < F) ? wl[k * F + j] : wr[k * F + (j - F)];
    }
    __syncthreads();

    int node = blockIdx.x * blockDim.x + threadIdx.x;
    if (node >= n) return;

    float xv[K];
    const float4* xr = reinterpret_cast<const float4*>(x + (size_t)node * K);
#pragma unroll
    for (int c = 0; c < K / 4; ++c) {
        float4 v = xr[c];
        xv[c * 4 + 0] = v.x; xv[c * 4 + 1] = v.y; xv[c * 4 + 2] = v.z; xv[c * 4 + 3] = v.w;
    }
    float acc[NC];
#pragma unroll
    for (int j = 0; j < NC; ++j) acc[j] = 0.f;
#pragma unroll
    for (int k = 0; k < K; ++k) {
        float a = xv[k];
#pragma unroll
        for (int j = 0; j < NC; ++j) acc[j] = fmaf(a, sB[k * NC + j], acc[j]);
    }
    float4* o = reinterpret_cast<float4*>(ylr + (size_t)node * NC);
#pragma unroll
    for (int c = 0; c < NC / 4; ++c)
        o[c] = make_float4(acc[c * 4], acc[c * 4 + 1], acc[c * 4 + 2], acc[c * 4 + 3]);
}

__global__ void proj3_pernode(const float* __restrict__ x, const float* __restrict__ wl,
                              const float* __restrict__ wr, float* __restrict__ ylr3, int n) {
    __shared__ float swl[16 * 9];
    __shared__ float swr[16 * 9];
    for (int i = threadIdx.x; i < 144; i += blockDim.x) {
        swl[i] = wl[i];
        swr[i] = wr[i];
    }
    __syncthreads();

    int node = blockIdx.x * blockDim.x + threadIdx.x;
    if (node >= n) return;

    float xv[16];
    const float4* xr = reinterpret_cast<const float4*>(x + (size_t)node * 16);
#pragma unroll
    for (int c = 0; c < 4; ++c) {
        float4 v = xr[c];
        xv[c * 4 + 0] = v.x; xv[c * 4 + 1] = v.y; xv[c * 4 + 2] = v.z; xv[c * 4 + 3] = v.w;
    }
    float al[9], ar[9];
#pragma unroll
    for (int j = 0; j < 9; ++j) { al[j] = 0.f; ar[j] = 0.f; }
#pragma unroll
    for (int k = 0; k < 16; ++k) {
        float a = xv[k];
#pragma unroll
        for (int j = 0; j < 9; ++j) {
            al[j] = fmaf(a, swl[k * 9 + j], al[j]);
            ar[j] = fmaf(a, swr[k * 9 + j], ar[j]);
        }
    }
    float4* o = reinterpret_cast<float4*>(ylr3 + (size_t)node * 32);
    o[0] = make_float4(al[0], al[1], al[2], al[3]);
    o[1] = make_float4(al[4], al[5], al[6], al[7]);
    o[2] = make_float4(al[8], 0.f, 0.f, 0.f);
    o[3] = make_float4(0.f, 0.f, 0.f, 0.f);
    o[4] = make_float4(ar[0], ar[1], ar[2], ar[3]);
    o[5] = make_float4(ar[4], ar[5], ar[6], ar[7]);
    ylr3[(size_t)node * 32 + 24] = ar[8];
}

// ---------------------------------------------------------------------------
// gather + combine (fused): warp per node.
// ---------------------------------------------------------------------------
template <int F, bool RELU>
__global__ void gather_combine(const float* __restrict__ ylr, const int* __restrict__ esrc,
                               const int* __restrict__ off, const int* __restrict__ cnt,
                               const float* __restrict__ bias, float* __restrict__ out, int n) {
    constexpr int CH = F / 4;
    constexpr int EPW = 32 / CH;
    int w = (blockIdx.x * blockDim.x + threadIdx.x) >> 5;
    if (w >= n) return;
    int lane = threadIdx.x & 31;
    int c = lane % CH, g = lane / CH;
    int start = off[w], deg = cnt[w];

    float4 acc = make_float4(0.f, 0.f, 0.f, 0.f);
    const float4* y4 = reinterpret_cast<const float4*>(ylr);
    for (int j = g; j < deg; j += EPW) {
        int s = __ldg(esrc + start + j);
        float4 v = y4[(size_t)s * (F / 2) + c];
        acc.x += v.x; acc.y += v.y; acc.z += v.z; acc.w += v.w;
    }
#pragma unroll
    for (int st = 16; st >= CH; st >>= 1) {
        acc.x += __shfl_xor_sync(0xFFFFFFFFu, acc.x, st);
        acc.y += __shfl_xor_sync(0xFFFFFFFFu, acc.y, st);
        acc.z += __shfl_xor_sync(0xFFFFFFFFu, acc.z, st);
        acc.w += __shfl_xor_sync(0xFFFFFFFFu, acc.w, st);
    }
    if (lane < CH) {
        float iv = __frcp_rn(fmaxf((float)deg, 1.0f));
        float4 r = y4[(size_t)w * (F / 2) + (F / 4) + c];
        float4 b = reinterpret_cast<const float4*>(bias)[c];
        float4 v;
        v.x = fmaf(acc.x, iv, r.x) + b.x;
        v.y = fmaf(acc.y, iv, r.y) + b.y;
        v.z = fmaf(acc.z, iv, r.z) + b.z;
        v.w = fmaf(acc.w, iv, r.w) + b.w;
        if (RELU) {
            v.x = fmaxf(v.x, 0.f); v.y = fmaxf(v.y, 0.f);
            v.z = fmaxf(v.z, 0.f); v.w = fmaxf(v.w, 0.f);
        }
        reinterpret_cast<float4*>(out)[(size_t)w * CH + c] = v;
    }
}

__global__ void gather9(const float* __restrict__ ylr3, const int* __restrict__ esrc,
                        const int* __restrict__ off, const int* __restrict__ cnt,
                        const float* __restrict__ bias, float* __restrict__ out, int n) {
    int w = (blockIdx.x * blockDim.x + threadIdx.x) >> 5;
    if (w >= n) return;
    int lane = threadIdx.x & 31;
    int c = lane % 4, g = lane / 4;
    int start = off[w], deg = cnt[w];

    float4 acc = make_float4(0.f, 0.f, 0.f, 0.f);
    const float4* y4 = reinterpret_cast<const float4*>(ylr3);
    for (int j = g; j < deg; j += 8) {
        int s = __ldg(esrc + start + j);
        float4 v = y4[(size_t)s * 8 + c];
        acc.x += v.x; acc.y += v.y; acc.z += v.z; acc.w += v.w;
    }
#pragma unroll
    for (int st = 16; st >= 4; st >>= 1) {
        acc.x += __shfl_xor_sync(0xFFFFFFFFu, acc.x, st);
        acc.y += __shfl_xor_sync(0xFFFFFFFFu, acc.y, st);
        acc.z += __shfl_xor_sync(0xFFFFFFFFu, acc.z, st);
        acc.w += __shfl_xor_sync(0xFFFFFFFFu, acc.w, st);
    }
    if (lane < 4) {
        float iv = __frcp_rn(fmaxf((float)deg, 1.0f));
        float a[4] = {acc.x, acc.y, acc.z, acc.w};
#pragma unroll
        for (int t = 0; t < 4; ++t) {
            int j = c * 4 + t;
            if (j < 9) {
                float yr = ylr3[(size_t)w * 32 + 16 + j];
                out[(size_t)w * 9 + j] = fmaf(a[t], iv, yr + __ldg(bias + j));
            }
        }
    }
}

// ---------------------------------------------------------------------------
// launch
// ---------------------------------------------------------------------------
extern "C" void kernel_launch(void* const* d_in, const int* in_sizes, int n_in,
                              void* d_out, int out_size) {
    const float* emb = (const float*)d_in[0];
    const int* ei = (const int*)d_in[1];
    const float* wl0 = (const float*)d_in[3];
    const float* wr0 = (const float*)d_in[4];
    const float* b0  = (const float*)d_in[5];
    const float* wl1 = (const float*)d_in[6];
    const float* wr1 = (const float*)d_in[7];
    const float* b1  = (const float*)d_in[8];
    const float* wl2 = (const float*)d_in[9];
    const float* wr2 = (const float*)d_in[10];
    const float* b2  = (const float*)d_in[11];
    const float* wl3 = (const float*)d_in[12];
    const float* wr3 = (const float*)d_in[13];
    const float* b3  = (const float*)d_in[14];
    float* out = (float*)d_out;

    const int n = in_sizes[0] / 128;
    const int E = in_sizes[1] / 2;
    const int* src = ei;
    const int* dst = ei + E;

    float *ylr, *xbuf;
    unsigned short *wth, *wtl;
    int *cnt, *off, *cur, *esrc, *bsum;
    cudaGetSymbolAddress((void**)&ylr, g_ylr);
    cudaGetSymbolAddress((void**)&xbuf, g_x);
    cudaGetSymbolAddress((void**)&wth, g_wth);
    cudaGetSymbolAddress((void**)&wtl, g_wtl);
    cudaGetSymbolAddress((void**)&cnt, g_cnt);
    cudaGetSymbolAddress((void**)&off, g_off);
    cudaGetSymbolAddress((void**)&cur, g_cur);
    cudaGetSymbolAddress((void**)&esrc, g_esrc);
    cudaGetSymbolAddress((void**)&bsum, g_bsum);

    auto cdiv = [](int a, int b) { return (a + b - 1) / b; };
    const int TB = 256;
    const int nb = cdiv(n, 512);

    const int SM_MMA = (2 * 64 * 136 + 2 * 128 * 136) * 2;  // 104448
    const int SM1 = (2 * 128 * 36 + 2 * 32 * 64) * 4;       // 53248
    cudaFuncSetAttribute((const void*)mma_proj0,
                         cudaFuncAttributeMaxDynamicSharedMemorySize, SM_MMA);
    cudaFuncSetAttribute((const void*)sgemm_proj_x2<64, 64, 128, 32, 4>,
                         cudaFuncAttributeMaxDynamicSharedMemorySize, SM1);

    static cudaStream_t s2 = nullptr;
    static cudaEvent_t evFork = nullptr, evJoin = nullptr;
    if (!s2) {
        cudaStreamCreateWithFlags(&s2, cudaStreamNonBlocking);
        cudaEventCreateWithFlags(&evFork, cudaEventDisableTiming);
        cudaEventCreateWithFlags(&evJoin, cudaEventDisableTiming);
    }

    // ---- fork: CSR build on s2 ----
    cudaEventRecord(evFork, 0);
    cudaStreamWaitEvent(s2, evFork, 0);

    zero_int<<<cdiv(n, 512), 512, 0, s2>>>(cnt, n);
    hist_kernel<<<cdiv(E, 512), 512, 0, s2>>>(dst, cnt, E);
    scan_block<<<nb, 512, 0, s2>>>(cnt, off, bsum, n);
    scan_sums<<<1, 512, 0, s2>>>(bsum, nb);
    scan_add<<<nb, 512, 0, s2>>>(off, bsum, cur, n);
    fill_kernel<<<cdiv(E, 512), 512, 0, s2>>>(src, dst, cur, esrc, E);
    cudaEventRecord(evJoin, s2);

    // ---- main: layer-0 tensor-core GEMM (persistent, W staged once/block) ----
    cvt_w_kernel<<<64, 256>>>(wl0, wr0, wth, wtl);
    const int ntiles = cdiv(n, 64);
    mma_proj0<<<296, 256, SM_MMA>>>(emb, wth, wtl, ylr, n, ntiles);

    // ---- join ----
    cudaStreamWaitEvent(0, evJoin, 0);

    gather_combine<64, true><<<cdiv(n * 32, TB), TB>>>(ylr, esrc, off, cnt, b0, xbuf, n);

    sgemm_proj_x2<64, 64, 128, 32, 4><<<cdiv(n, 128), 128, SM1>>>(xbuf, wl1, wr1, ylr, n);
    gather_combine<32, true><<<cdiv(n * 32, TB), TB>>>(ylr, esrc, off, cnt, b1, xbuf, n);

    proj_pernode<32, 16><<<cdiv(n, TB), TB>>>(xbuf, wl2, wr2, ylr, n);
    gather_combine<16, true><<<cdiv(n * 32, TB), TB>>>(ylr, esrc, off, cnt, b2, xbuf, n);

    proj3_pernode<<<cdiv(n, TB), TB>>>(xbuf, wl3, wr3, ylr, n);
    gather9<<<cdiv(n * 32, TB), TB>>>(ylr, esrc, off, cnt, b3, out, n);
}

// round 12
// speedup vs baseline: 1.2570x; 1.0450x over previous
#include <cuda_runtime.h>
#include <cuda_bf16.h>
#include <cstdint>

#define NMAX 100000
#define EMAX 600000

// Scratch (static device globals — allocation-free per harness rules)
__device__ __align__(16) float g_ylr[NMAX * 128];  // projected [y_l | y_r]
__device__ __align__(16) float g_x[NMAX * 64];     // layer activations
__device__ __align__(16) unsigned short g_wth[128 * 128];  // W0 hi bf16, n-major [n][k]
__device__ __align__(16) unsigned short g_wtl[128 * 128];  // W0 lo bf16, n-major [n][k]
__device__ __align__(16) unsigned short g_wth1[64 * 64];   // W1 hi bf16, n-major [n][k]
__device__ __align__(16) unsigned short g_wtl1[64 * 64];   // W1 lo bf16, n-major [n][k]
__device__ int g_cnt[NMAX];
__device__ int g_off[NMAX];
__device__ int g_cur[NMAX];
__device__ int g_esrc[EMAX];
__device__ int g_bsum[512];

// ---------------------------------------------------------------------------
// CSR build
// ---------------------------------------------------------------------------
__global__ void zero_int(int* __restrict__ p, int n) {
    int i = blockIdx.x * blockDim.x + threadIdx.x;
    if (i < n) p[i] = 0;
}

__global__ void hist_kernel(const int* __restrict__ dst, int* __restrict__ cnt, int E) {
    int i = blockIdx.x * blockDim.x + threadIdx.x;
    if (i < E) atomicAdd(&cnt[dst[i]], 1);
}

__device__ __forceinline__ int block_exscan_512(int v, int tid, int* warp_sums, int* total) {
    int lane = tid & 31, wid = tid >> 5;
    int inc = v;
#pragma unroll
    for (int st = 1; st < 32; st <<= 1) {
        int t = __shfl_up_sync(0xFFFFFFFFu, inc, st);
        if (lane >= st) inc += t;
    }
    if (lane == 31) warp_sums[wid] = inc;
    __syncthreads();
    if (wid == 0) {
        int ws = (lane < 16) ? warp_sums[lane] : 0;
#pragma unroll
        for (int st = 1; st < 16; st <<= 1) {
            int t = __shfl_up_sync(0xFFFFFFFFu, ws, st);
            if (lane >= st) ws += t;
        }
        if (lane < 16) warp_sums[lane] = ws;
    }
    __syncthreads();
    int base = (wid > 0) ? warp_sums[wid - 1] : 0;
    if (total) *total = warp_sums[15];
    return base + inc - v;
}

__global__ void scan_block(const int* __restrict__ cnt, int* __restrict__ off,
                           int* __restrict__ bsum, int n) {
    __shared__ int ws[16];
    int i = blockIdx.x * 512 + threadIdx.x;
    int v = (i < n) ? cnt[i] : 0;
    int total;
    int ex = block_exscan_512(v, threadIdx.x, ws, &total);
    if (i < n) off[i] = ex;
    if (threadIdx.x == 0) bsum[blockIdx.x] = total;
}

__global__ void scan_sums(int* __restrict__ bsum, int nb) {
    __shared__ int ws[16];
    int v = (threadIdx.x < nb) ? bsum[threadIdx.x] : 0;
    int ex = block_exscan_512(v, threadIdx.x, ws, nullptr);
    if (threadIdx.x < nb) bsum[threadIdx.x] = ex;
}

__global__ void scan_add(int* __restrict__ off, const int* __restrict__ bsum,
                         int* __restrict__ cur, int n) {
    int i = blockIdx.x * 512 + threadIdx.x;
    if (i < n) {
        int o = off[i] + bsum[blockIdx.x];
        off[i] = o;
        cur[i] = o;
    }
}

__global__ void fill_kernel(const int* __restrict__ src, const int* __restrict__ dst,
                            int* __restrict__ cur, int* __restrict__ esrc, int E) {
    int e = blockIdx.x * blockDim.x + threadIdx.x;
    if (e < E) {
        int p = atomicAdd(&cur[dst[e]], 1);
        esrc[p] = src[e];
    }
}

// ---------------------------------------------------------------------------
// W conversions: combined [k][n] -> n-major bf16 hi/lo wt[n*K + k]
// ---------------------------------------------------------------------------
__global__ void cvt_w_kernel(const float* __restrict__ wl, const float* __restrict__ wr,
                             unsigned short* __restrict__ wth, unsigned short* __restrict__ wtl) {
    int i = blockIdx.x * blockDim.x + threadIdx.x;
    if (i >= 128 * 128) return;
    int nn = i >> 7, k = i & 127;
    float w = (nn < 64) ? wl[k * 64 + nn] : wr[k * 64 + (nn - 64)];
    __nv_bfloat16 h = __float2bfloat16(w);
    __nv_bfloat16 l = __float2bfloat16(w - __bfloat162float(h));
    wth[i] = *reinterpret_cast<unsigned short*>(&h);
    wtl[i] = *reinterpret_cast<unsigned short*>(&l);
}

__global__ void cvt_w1_kernel(const float* __restrict__ wl, const float* __restrict__ wr,
                              unsigned short* __restrict__ wth, unsigned short* __restrict__ wtl) {
    int i = blockIdx.x * blockDim.x + threadIdx.x;
    if (i >= 64 * 64) return;
    int nn = i >> 6, k = i & 63;
    float w = (nn < 32) ? wl[k * 32 + nn] : wr[k * 32 + (nn - 32)];
    __nv_bfloat16 h = __float2bfloat16(w);
    __nv_bfloat16 l = __float2bfloat16(w - __bfloat162float(h));
    wth[i] = *reinterpret_cast<unsigned short*>(&h);
    wtl[i] = *reinterpret_cast<unsigned short*>(&l);
}

// ---------------------------------------------------------------------------
// mma helpers
// ---------------------------------------------------------------------------
__device__ __forceinline__ void mma16816(float* d, const unsigned* a,
                                         unsigned b0, unsigned b1) {
    asm volatile(
        "mma.sync.aligned.m16n8k16.row.col.f32.bf16.bf16.f32 "
        "{%0,%1,%2,%3}, {%4,%5,%6,%7}, {%8,%9}, {%0,%1,%2,%3};"
        : "+f"(d[0]), "+f"(d[1]), "+f"(d[2]), "+f"(d[3])
        : "r"(a[0]), "r"(a[1]), "r"(a[2]), "r"(a[3]), "r"(b0), "r"(b1));
}

__device__ __forceinline__ unsigned pack2_hi(float a, float b) {
    __nv_bfloat162 t;
    t.x = __float2bfloat16(a);
    t.y = __float2bfloat16(b);
    return *reinterpret_cast<unsigned*>(&t);
}

// ---------------------------------------------------------------------------
// layer-0 tensor-core GEMM (persistent): ylr[n x 128] = X[n x 128] @ W[128 x 128]
// 3-term bf16 split, fp32 accum. W staged once per persistent block; next
// tile's fp32 X prefetched in registers. BM=64, 2 blocks/SM.
// ---------------------------------------------------------------------------
__global__ void __launch_bounds__(256, 2)
mma_proj0(const float* __restrict__ x, const unsigned short* __restrict__ wth,
          const unsigned short* __restrict__ wtl, float* __restrict__ ylr,
          int n, int ntiles) {
    constexpr int S = 136;
    extern __shared__ __align__(16) unsigned short smu[];
    unsigned short* sXh = smu;              // [64][S]
    unsigned short* sXl = sXh + 64 * S;
    unsigned short* sWh = sXl + 64 * S;     // n-major [128][S]
    unsigned short* sWl = sWh + 128 * S;

    const int tid = threadIdx.x;
    const int lane = tid & 31;
    const int warp = tid >> 5;
    const int warpm = warp >> 1;
    const int warpn = warp & 1;
    const int g = lane >> 2;
    const int t2 = (lane & 3) * 2;

    for (int idx = tid; idx < 128 * 16; idx += 256) {
        int r = idx >> 4, c = (idx & 15) * 8;
        *reinterpret_cast<uint4*>(&sWh[r * S + c]) =
            *reinterpret_cast<const uint4*>(&wth[r * 128 + c]);
        *reinterpret_cast<uint4*>(&sWl[r * S + c]) =
            *reinterpret_cast<const uint4*>(&wtl[r * 128 + c]);
    }

    float4 xf[8];
    auto load_x = [&](int tile) {
        const int nb = tile * 64;
        const int mrem = n - nb;
#pragma unroll
        for (int i = 0; i < 8; ++i) {
            int idx = tid + i * 256;
            int r = idx >> 5, cc = (idx & 31) * 4;
            float4 v = make_float4(0.f, 0.f, 0.f, 0.f);
            if (r < mrem)
                v = *reinterpret_cast<const float4*>(&x[(size_t)(nb + r) * 128 + cc]);
            xf[i] = v;
        }
    };

    int tile = blockIdx.x;
    if (tile < ntiles) load_x(tile);

    while (tile < ntiles) {
#pragma unroll
        for (int i = 0; i < 8; ++i) {
            int idx = tid + i * 256;
            int r = idx >> 5, cc = (idx & 31) * 4;
            float4 v = xf[i];
            __nv_bfloat16 h0 = __float2bfloat16(v.x), h1 = __float2bfloat16(v.y);
            __nv_bfloat16 h2 = __float2bfloat16(v.z), h3 = __float2bfloat16(v.w);
            uint2 ph, pl;
            __nv_bfloat162 t;
            t.x = h0; t.y = h1; ph.x = *reinterpret_cast<unsigned*>(&t);
            t.x = h2; t.y = h3; ph.y = *reinterpret_cast<unsigned*>(&t);
            pl.x = pack2_hi(v.x - __bfloat162float(h0), v.y - __bfloat162float(h1));
            pl.y = pack2_hi(v.z - __bfloat162float(h2), v.w - __bfloat162float(h3));
            *reinterpret_cast<uint2*>(&sXh[r * S + cc]) = ph;
            *reinterpret_cast<uint2*>(&sXl[r * S + cc]) = pl;
        }
        __syncthreads();

        const int nb = tile * 64;
        const int next = tile + gridDim.x;
        if (next < ntiles) load_x(next);

        float acc[8][4];
#pragma unroll
        for (int nt = 0; nt < 8; ++nt)
#pragma unroll
            for (int t = 0; t < 4; ++t) acc[nt][t] = 0.f;

#pragma unroll
        for (int s = 0; s < 8; ++s) {
            const int k0 = s * 16;
            unsigned ah[4], al[4];
            {
                int r = warpm * 16 + g;
                ah[0] = *reinterpret_cast<const unsigned*>(&sXh[r * S + k0 + t2]);
                ah[1] = *reinterpret_cast<const unsigned*>(&sXh[(r + 8) * S + k0 + t2]);
                ah[2] = *reinterpret_cast<const unsigned*>(&sXh[r * S + k0 + t2 + 8]);
                ah[3] = *reinterpret_cast<const unsigned*>(&sXh[(r + 8) * S + k0 + t2 + 8]);
                al[0] = *reinterpret_cast<const unsigned*>(&sXl[r * S + k0 + t2]);
                al[1] = *reinterpret_cast<const unsigned*>(&sXl[(r + 8) * S + k0 + t2]);
                al[2] = *reinterpret_cast<const unsigned*>(&sXl[r * S + k0 + t2 + 8]);
                al[3] = *reinterpret_cast<const unsigned*>(&sXl[(r + 8) * S + k0 + t2 + 8]);
            }
#pragma unroll
            for (int nt = 0; nt < 8; ++nt) {
                int nn = warpn * 64 + nt * 8 + g;
                unsigned bh0 = *reinterpret_cast<const unsigned*>(&sWh[nn * S + k0 + t2]);
                unsigned bh1 = *reinterpret_cast<const unsigned*>(&sWh[nn * S + k0 + t2 + 8]);
                unsigned bl0 = *reinterpret_cast<const unsigned*>(&sWl[nn * S + k0 + t2]);
                unsigned bl1 = *reinterpret_cast<const unsigned*>(&sWl[nn * S + k0 + t2 + 8]);
                mma16816(acc[nt], ah, bh0, bh1);
                mma16816(acc[nt], al, bh0, bh1);
                mma16816(acc[nt], ah, bl0, bl1);
            }
        }

#pragma unroll
        for (int nt = 0; nt < 8; ++nt) {
            int col = warpn * 64 + nt * 8 + t2;
            int node0 = nb + warpm * 16 + g;
            int node1 = node0 + 8;
            if (node0 < n) {
                float2 v = make_float2(acc[nt][0], acc[nt][1]);
                *reinterpret_cast<float2*>(&ylr[(size_t)node0 * 128 + col]) = v;
            }
            if (node1 < n) {
                float2 v = make_float2(acc[nt][2], acc[nt][3]);
                *reinterpret_cast<float2*>(&ylr[(size_t)node1 * 128 + col]) = v;
            }
        }

        __syncthreads();
        tile = next;
    }
}

// ---------------------------------------------------------------------------
// layer-1 tensor-core GEMM (persistent): ylr[n x 64] = X[n x 64] @ W[64 x 64]
// Same recipe: 3-term bf16 split, W once per block, register-prefetched X.
// BM=64, S=72 (conflict-free), 3 blocks/SM.
// ---------------------------------------------------------------------------
__global__ void __launch_bounds__(256, 3)
mma_proj1(const float* __restrict__ x, const unsigned short* __restrict__ wth,
          const unsigned short* __restrict__ wtl, float* __restrict__ ylr,
          int n, int ntiles) {
    constexpr int S = 72;  // halves; 36 words == 4 mod 32 -> conflict-free
    extern __shared__ __align__(16) unsigned short smu[];
    unsigned short* sXh = smu;              // [64][S]
    unsigned short* sXl = sXh + 64 * S;
    unsigned short* sWh = sXl + 64 * S;     // n-major [64][S]
    unsigned short* sWl = sWh + 64 * S;

    const int tid = threadIdx.x;
    const int lane = tid & 31;
    const int warp = tid >> 5;
    const int warpm = warp >> 1;   // 0..3: one m16 tile each
    const int warpn = warp & 1;    // 0..1: 32 cols each
    const int g = lane >> 2;
    const int t2 = (lane & 3) * 2;

    // stage W once: 64 rows x 8 uint4-chunks per array
    for (int idx = tid; idx < 64 * 8; idx += 256) {
        int r = idx >> 3, c = (idx & 7) * 8;
        *reinterpret_cast<uint4*>(&sWh[r * S + c]) =
            *reinterpret_cast<const uint4*>(&wth[r * 64 + c]);
        *reinterpret_cast<uint4*>(&sWl[r * S + c]) =
            *reinterpret_cast<const uint4*>(&wtl[r * 64 + c]);
    }

    // X tile: 64 rows x 16 float4-chunks = 1024 chunks; 4 per thread
    float4 xf[4];
    auto load_x = [&](int tile) {
        const int nb = tile * 64;
        const int mrem = n - nb;
#pragma unroll
        for (int i = 0; i < 4; ++i) {
            int idx = tid + i * 256;
            int r = idx >> 4, cc = (idx & 15) * 4;
            float4 v = make_float4(0.f, 0.f, 0.f, 0.f);
            if (r < mrem)
                v = *reinterpret_cast<const float4*>(&x[(size_t)(nb + r) * 64 + cc]);
            xf[i] = v;
        }
    };

    int tile = blockIdx.x;
    if (tile < ntiles) load_x(tile);

    while (tile < ntiles) {
#pragma unroll
        for (int i = 0; i < 4; ++i) {
            int idx = tid + i * 256;
            int r = idx >> 4, cc = (idx & 15) * 4;
            float4 v = xf[i];
            __nv_bfloat16 h0 = __float2bfloat16(v.x), h1 = __float2bfloat16(v.y);
            __nv_bfloat16 h2 = __float2bfloat16(v.z), h3 = __float2bfloat16(v.w);
            uint2 ph, pl;
            __nv_bfloat162 t;
            t.x = h0; t.y = h1; ph.x = *reinterpret_cast<unsigned*>(&t);
            t.x = h2; t.y = h3; ph.y = *reinterpret_cast<unsigned*>(&t);
            pl.x = pack2_hi(v.x - __bfloat162float(h0), v.y - __bfloat162float(h1));
            pl.y = pack2_hi(v.z - __bfloat162float(h2), v.w - __bfloat162float(h3));
            *reinterpret_cast<uint2*>(&sXh[r * S + cc]) = ph;
            *reinterpret_cast<uint2*>(&sXl[r * S + cc]) = pl;
        }
        __syncthreads();

        const int nb = tile * 64;
        const int next = tile + gridDim.x;
        if (next < ntiles) load_x(next);

        float acc[4][4];
#pragma unroll
        for (int nt = 0; nt < 4; ++nt)
#pragma unroll
            for (int t = 0; t < 4; ++t) acc[nt][t] = 0.f;

#pragma unroll
        for (int s = 0; s < 4; ++s) {
            const int k0 = s * 16;
            unsigned ah[4], al[4];
            {
                int r = warpm * 16 + g;
                ah[0] = *reinterpret_cast<const unsigned*>(&sXh[r * S + k0 + t2]);
                ah[1] = *reinterpret_cast<const unsigned*>(&sXh[(r + 8) * S + k0 + t2]);
                ah[2] = *reinterpret_cast<const unsigned*>(&sXh[r * S + k0 + t2 + 8]);
                ah[3] = *reinterpret_cast<const unsigned*>(&sXh[(r + 8) * S + k0 + t2 + 8]);
                al[0] = *reinterpret_cast<const unsigned*>(&sXl[r * S + k0 + t2]);
                al[1] = *reinterpret_cast<const unsigned*>(&sXl[(r + 8) * S + k0 + t2]);
                al[2] = *reinterpret_cast<const unsigned*>(&sXl[r * S + k0 + t2 + 8]);
                al[3] = *reinterpret_cast<const unsigned*>(&sXl[(r + 8) * S + k0 + t2 + 8]);
            }
#pragma unroll
            for (int nt = 0; nt < 4; ++nt) {
                int nn = warpn * 32 + nt * 8 + g;
                unsigned bh0 = *reinterpret_cast<const unsigned*>(&sWh[nn * S + k0 + t2]);
                unsigned bh1 = *reinterpret_cast<const unsigned*>(&sWh[nn * S + k0 + t2 + 8]);
                unsigned bl0 = *reinterpret_cast<const unsigned*>(&sWl[nn * S + k0 + t2]);
                unsigned bl1 = *reinterpret_cast<const unsigned*>(&sWl[nn * S + k0 + t2 + 8]);
                mma16816(acc[nt], ah, bh0, bh1);
                mma16816(acc[nt], al, bh0, bh1);
                mma16816(acc[nt], ah, bl0, bl1);
            }
        }

#pragma unroll
        for (int nt = 0; nt < 4; ++nt) {
            int col = warpn * 32 + nt * 8 + t2;
            int node0 = nb + warpm * 16 + g;
            int node1 = node0 + 8;
            if (node0 < n) {
                float2 v = make_float2(acc[nt][0], acc[nt][1]);
                *reinterpret_cast<float2*>(&ylr[(size_t)node0 * 64 + col]) = v;
            }
            if (node1 < n) {
                float2 v = make_float2(acc[nt][2], acc[nt][3]);
                *reinterpret_cast<float2*>(&ylr[(size_t)node1 * 64 + col]) = v;
            }
        }

        __syncthreads();
        tile = next;
    }
}

// ---------------------------------------------------------------------------
// per-node projection for small layers
// ---------------------------------------------------------------------------
template <int K, int F>
__global__ void proj_pernode(const float* __restrict__ x, const float* __restrict__ wl,
                             const float* __restrict__ wr, float* __restrict__ ylr, int n) {
    constexpr int NC = 2 * F;
    __shared__ float sB[K * NC];
    for (int i = threadIdx.x; i < K * NC; i += blockDim.x) {
        int k = i / NC, j = i % NC;
        sB[i] = (j < F) ? wl[k * F + j] : wr[k * F + (j - F)];
    }
    __syncthreads();

    int node = blockIdx.x * blockDim.x + threadIdx.x;
    if (node >= n) return;

    float xv[K];
    const float4* xr = reinterpret_cast<const float4*>(x + (size_t)node * K);
#pragma unroll
    for (int c = 0; c < K / 4; ++c) {
        float4 v = xr[c];
        xv[c * 4 + 0] = v.x; xv[c * 4 + 1] = v.y; xv[c * 4 + 2] = v.z; xv[c * 4 + 3] = v.w;
    }
    float acc[NC];
#pragma unroll
    for (int j = 0; j < NC; ++j) acc[j] = 0.f;
#pragma unroll
    for (int k = 0; k < K; ++k) {
        float a = xv[k];
#pragma unroll
        for (int j = 0; j < NC; ++j) acc[j] = fmaf(a, sB[k * NC + j], acc[j]);
    }
    float4* o = reinterpret_cast<float4*>(ylr + (size_t)node * NC);
#pragma unroll
    for (int c = 0; c < NC / 4; ++c)
        o[c] = make_float4(acc[c * 4], acc[c * 4 + 1], acc[c * 4 + 2], acc[c * 4 + 3]);
}

__global__ void proj3_pernode(const float* __restrict__ x, const float* __restrict__ wl,
                              const float* __restrict__ wr, float* __restrict__ ylr3, int n) {
    __shared__ float swl[16 * 9];
    __shared__ float swr[16 * 9];
    for (int i = threadIdx.x; i < 144; i += blockDim.x) {
        swl[i] = wl[i];
        swr[i] = wr[i];
    }
    __syncthreads();

    int node = blockIdx.x * blockDim.x + threadIdx.x;
    if (node >= n) return;

    float xv[16];
    const float4* xr = reinterpret_cast<const float4*>(x + (size_t)node * 16);
#pragma unroll
    for (int c = 0; c < 4; ++c) {
        float4 v = xr[c];
        xv[c * 4 + 0] = v.x; xv[c * 4 + 1] = v.y; xv[c * 4 + 2] = v.z; xv[c * 4 + 3] = v.w;
    }
    float al[9], ar[9];
#pragma unroll
    for (int j = 0; j < 9; ++j) { al[j] = 0.f; ar[j] = 0.f; }
#pragma unroll
    for (int k = 0; k < 16; ++k) {
        float a = xv[k];
#pragma unroll
        for (int j = 0; j < 9; ++j) {
            al[j] = fmaf(a, swl[k * 9 + j], al[j]);
            ar[j] = fmaf(a, swr[k * 9 + j], ar[j]);
        }
    }
    float4* o = reinterpret_cast<float4*>(ylr3 + (size_t)node * 32);
    o[0] = make_float4(al[0], al[1], al[2], al[3]);
    o[1] = make_float4(al[4], al[5], al[6], al[7]);
    o[2] = make_float4(al[8], 0.f, 0.f, 0.f);
    o[3] = make_float4(0.f, 0.f, 0.f, 0.f);
    o[4] = make_float4(ar[0], ar[1], ar[2], ar[3]);
    o[5] = make_float4(ar[4], ar[5], ar[6], ar[7]);
    ylr3[(size_t)node * 32 + 24] = ar[8];
}

// ---------------------------------------------------------------------------
// gather + combine (fused): warp per node.
// ---------------------------------------------------------------------------
template <int F, bool RELU>
__global__ void gather_combine(const float* __restrict__ ylr, const int* __restrict__ esrc,
                               const int* __restrict__ off, const int* __restrict__ cnt,
                               const float* __restrict__ bias, float* __restrict__ out, int n) {
    constexpr int CH = F / 4;
    constexpr int EPW = 32 / CH;
    int w = (blockIdx.x * blockDim.x + threadIdx.x) >> 5;
    if (w >= n) return;
    int lane = threadIdx.x & 31;
    int c = lane % CH, g = lane / CH;
    int start = off[w], deg = cnt[w];

    float4 acc = make_float4(0.f, 0.f, 0.f, 0.f);
    const float4* y4 = reinterpret_cast<const float4*>(ylr);
    for (int j = g; j < deg; j += EPW) {
        int s = __ldg(esrc + start + j);
        float4 v = y4[(size_t)s * (F / 2) + c];
        acc.x += v.x; acc.y += v.y; acc.z += v.z; acc.w += v.w;
    }
#pragma unroll
    for (int st = 16; st >= CH; st >>= 1) {
        acc.x += __shfl_xor_sync(0xFFFFFFFFu, acc.x, st);
        acc.y += __shfl_xor_sync(0xFFFFFFFFu, acc.y, st);
        acc.z += __shfl_xor_sync(0xFFFFFFFFu, acc.z, st);
        acc.w += __shfl_xor_sync(0xFFFFFFFFu, acc.w, st);
    }
    if (lane < CH) {
        float iv = __frcp_rn(fmaxf((float)deg, 1.0f));
        float4 r = y4[(size_t)w * (F / 2) + (F / 4) + c];
        float4 b = reinterpret_cast<const float4*>(bias)[c];
        float4 v;
        v.x = fmaf(acc.x, iv, r.x) + b.x;
        v.y = fmaf(acc.y, iv, r.y) + b.y;
        v.z = fmaf(acc.z, iv, r.z) + b.z;
        v.w = fmaf(acc.w, iv, r.w) + b.w;
        if (RELU) {
            v.x = fmaxf(v.x, 0.f); v.y = fmaxf(v.y, 0.f);
            v.z = fmaxf(v.z, 0.f); v.w = fmaxf(v.w, 0.f);
        }
        reinterpret_cast<float4*>(out)[(size_t)w * CH + c] = v;
    }
}

__global__ void gather9(const float* __restrict__ ylr3, const int* __restrict__ esrc,
                        const int* __restrict__ off, const int* __restrict__ cnt,
                        const float* __restrict__ bias, float* __restrict__ out, int n) {
    int w = (blockIdx.x * blockDim.x + threadIdx.x) >> 5;
    if (w >= n) return;
    int lane = threadIdx.x & 31;
    int c = lane % 4, g = lane / 4;
    int start = off[w], deg = cnt[w];

    float4 acc = make_float4(0.f, 0.f, 0.f, 0.f);
    const float4* y4 = reinterpret_cast<const float4*>(ylr3);
    for (int j = g; j < deg; j += 8) {
        int s = __ldg(esrc + start + j);
        float4 v = y4[(size_t)s * 8 + c];
        acc.x += v.x; acc.y += v.y; acc.z += v.z; acc.w += v.w;
    }
#pragma unroll
    for (int st = 16; st >= 4; st >>= 1) {
        acc.x += __shfl_xor_sync(0xFFFFFFFFu, acc.x, st);
        acc.y += __shfl_xor_sync(0xFFFFFFFFu, acc.y, st);
        acc.z += __shfl_xor_sync(0xFFFFFFFFu, acc.z, st);
        acc.w += __shfl_xor_sync(0xFFFFFFFFu, acc.w, st);
    }
    if (lane < 4) {
        float iv = __frcp_rn(fmaxf((float)deg, 1.0f));
        float a[4] = {acc.x, acc.y, acc.z, acc.w};
#pragma unroll
        for (int t = 0; t < 4; ++t) {
            int j = c * 4 + t;
            if (j < 9) {
                float yr = ylr3[(size_t)w * 32 + 16 + j];
                out[(size_t)w * 9 + j] = fmaf(a[t], iv, yr + __ldg(bias + j));
            }
        }
    }
}

// ---------------------------------------------------------------------------
// launch
// ---------------------------------------------------------------------------
extern "C" void kernel_launch(void* const* d_in, const int* in_sizes, int n_in,
                              void* d_out, int out_size) {
    const float* emb = (const float*)d_in[0];
    const int* ei = (const int*)d_in[1];
    const float* wl0 = (const float*)d_in[3];
    const float* wr0 = (const float*)d_in[4];
    const float* b0  = (const float*)d_in[5];
    const float* wl1 = (const float*)d_in[6];
    const float* wr1 = (const float*)d_in[7];
    const float* b1  = (const float*)d_in[8];
    const float* wl2 = (const float*)d_in[9];
    const float* wr2 = (const float*)d_in[10];
    const float* b2  = (const float*)d_in[11];
    const float* wl3 = (const float*)d_in[12];
    const float* wr3 = (const float*)d_in[13];
    const float* b3  = (const float*)d_in[14];
    float* out = (float*)d_out;

    const int n = in_sizes[0] / 128;
    const int E = in_sizes[1] / 2;
    const int* src = ei;
    const int* dst = ei + E;

    float *ylr, *xbuf;
    unsigned short *wth, *wtl, *wth1, *wtl1;
    int *cnt, *off, *cur, *esrc, *bsum;
    cudaGetSymbolAddress((void**)&ylr, g_ylr);
    cudaGetSymbolAddress((void**)&xbuf, g_x);
    cudaGetSymbolAddress((void**)&wth, g_wth);
    cudaGetSymbolAddress((void**)&wtl, g_wtl);
    cudaGetSymbolAddress((void**)&wth1, g_wth1);
    cudaGetSymbolAddress((void**)&wtl1, g_wtl1);
    cudaGetSymbolAddress((void**)&cnt, g_cnt);
    cudaGetSymbolAddress((void**)&off, g_off);
    cudaGetSymbolAddress((void**)&cur, g_cur);
    cudaGetSymbolAddress((void**)&esrc, g_esrc);
    cudaGetSymbolAddress((void**)&bsum, g_bsum);

    auto cdiv = [](int a, int b) { return (a + b - 1) / b; };
    const int TB = 256;
    const int nb = cdiv(n, 512);

    const int SM_MMA0 = (2 * 64 * 136 + 2 * 128 * 136) * 2;  // 104448
    const int SM_MMA1 = (4 * 64 * 72) * 2;                   // 36864
    cudaFuncSetAttribute((const void*)mma_proj0,
                         cudaFuncAttributeMaxDynamicSharedMemorySize, SM_MMA0);
    cudaFuncSetAttribute((const void*)mma_proj1,
                         cudaFuncAttributeMaxDynamicSharedMemorySize, SM_MMA1);

    static cudaStream_t s2 = nullptr;
    static cudaEvent_t evFork = nullptr, evJoin = nullptr;
    if (!s2) {
        cudaStreamCreateWithFlags(&s2, cudaStreamNonBlocking);
        cudaEventCreateWithFlags(&evFork, cudaEventDisableTiming);
        cudaEventCreateWithFlags(&evJoin, cudaEventDisableTiming);
    }

    // ---- fork: CSR build + W1 conversion on s2 (hidden under proj0) ----
    cudaEventRecord(evFork, 0);
    cudaStreamWaitEvent(s2, evFork, 0);

    cvt_w1_kernel<<<16, 256, 0, s2>>>(wl1, wr1, wth1, wtl1);
    zero_int<<<cdiv(n, 512), 512, 0, s2>>>(cnt, n);
    hist_kernel<<<cdiv(E, 512), 512, 0, s2>>>(dst, cnt, E);
    scan_block<<<nb, 512, 0, s2>>>(cnt, off, bsum, n);
    scan_sums<<<1, 512, 0, s2>>>(bsum, nb);
    scan_add<<<nb, 512, 0, s2>>>(off, bsum, cur, n);
    fill_kernel<<<cdiv(E, 512), 512, 0, s2>>>(src, dst, cur, esrc, E);
    cudaEventRecord(evJoin, s2);

    // ---- main: layer-0 tensor-core GEMM (persistent) ----
    cvt_w_kernel<<<64, 256>>>(wl0, wr0, wth, wtl);
    mma_proj0<<<296, 256, SM_MMA0>>>(emb, wth, wtl, ylr, n, cdiv(n, 64));

    // ---- join ----
    cudaStreamWaitEvent(0, evJoin, 0);

    gather_combine<64, true><<<cdiv(n * 32, TB), TB>>>(ylr, esrc, off, cnt, b0, xbuf, n);

    mma_proj1<<<444, 256, SM_MMA1>>>(xbuf, wth1, wtl1, ylr, n, cdiv(n, 64));
    gather_combine<32, true><<<cdiv(n * 32, TB), TB>>>(ylr, esrc, off, cnt, b1, xbuf, n);

    proj_pernode<32, 16><<<cdiv(n, TB), TB>>>(xbuf, wl2, wr2, ylr, n);
    gather_combine<16, true><<<cdiv(n * 32, TB), TB>>>(ylr, esrc, off, cnt, b2, xbuf, n);

    proj3_pernode<<<cdiv(n, TB), TB>>>(xbuf, wl3, wr3, ylr, n);
    gather9<<<cdiv(n * 32, TB), TB>>>(ylr, esrc, off, cnt, b3, out, n);
}

// round 13
// speedup vs baseline: 1.3172x; 1.0478x over previous
#include <cuda_runtime.h>
#include <cuda_bf16.h>
#include <cstdint>

#define NMAX 100000
#define EMAX 600000

// Scratch (static device globals — allocation-free per harness rules)
__device__ __align__(16) float g_ylr[NMAX * 128];  // projected [y_l | y_r]
__device__ __align__(16) float g_x[NMAX * 64];     // layer activations
__device__ __align__(16) unsigned short g_wth[128 * 128];  // W0 hi bf16, n-major [n][k]
__device__ __align__(16) unsigned short g_wtl[128 * 128];  // W0 lo bf16, n-major [n][k]
__device__ __align__(16) unsigned short g_wth1[64 * 64];   // W1 hi bf16, n-major [n][k]
__device__ __align__(16) unsigned short g_wtl1[64 * 64];   // W1 lo bf16, n-major [n][k]
__device__ int g_cnt[NMAX];
__device__ int g_off[NMAX];
__device__ int g_cur[NMAX];
__device__ int g_esrc[EMAX];
__device__ int g_bsum[512];

// ---------------------------------------------------------------------------
// CSR build
// ---------------------------------------------------------------------------
__global__ void zero_int(int* __restrict__ p, int n) {
    int i = blockIdx.x * blockDim.x + threadIdx.x;
    if (i < n) p[i] = 0;
}

__global__ void hist_kernel(const int* __restrict__ dst, int* __restrict__ cnt, int E) {
    int i = blockIdx.x * blockDim.x + threadIdx.x;
    if (i < E) atomicAdd(&cnt[dst[i]], 1);
}

__device__ __forceinline__ int block_exscan_512(int v, int tid, int* warp_sums, int* total) {
    int lane = tid & 31, wid = tid >> 5;
    int inc = v;
#pragma unroll
    for (int st = 1; st < 32; st <<= 1) {
        int t = __shfl_up_sync(0xFFFFFFFFu, inc, st);
        if (lane >= st) inc += t;
    }
    if (lane == 31) warp_sums[wid] = inc;
    __syncthreads();
    if (wid == 0) {
        int ws = (lane < 16) ? warp_sums[lane] : 0;
#pragma unroll
        for (int st = 1; st < 16; st <<= 1) {
            int t = __shfl_up_sync(0xFFFFFFFFu, ws, st);
            if (lane >= st) ws += t;
        }
        if (lane < 16) warp_sums[lane] = ws;
    }
    __syncthreads();
    int base = (wid > 0) ? warp_sums[wid - 1] : 0;
    if (total) *total = warp_sums[15];
    return base + inc - v;
}

__global__ void scan_block(const int* __restrict__ cnt, int* __restrict__ off,
                           int* __restrict__ bsum, int n) {
    __shared__ int ws[16];
    int i = blockIdx.x * 512 + threadIdx.x;
    int v = (i < n) ? cnt[i] : 0;
    int total;
    int ex = block_exscan_512(v, threadIdx.x, ws, &total);
    if (i < n) off[i] = ex;
    if (threadIdx.x == 0) bsum[blockIdx.x] = total;
}

__global__ void scan_sums(int* __restrict__ bsum, int nb) {
    __shared__ int ws[16];
    int v = (threadIdx.x < nb) ? bsum[threadIdx.x] : 0;
    int ex = block_exscan_512(v, threadIdx.x, ws, nullptr);
    if (threadIdx.x < nb) bsum[threadIdx.x] = ex;
}

__global__ void scan_add(int* __restrict__ off, const int* __restrict__ bsum,
                         int* __restrict__ cur, int n) {
    int i = blockIdx.x * 512 + threadIdx.x;
    if (i < n) {
        int o = off[i] + bsum[blockIdx.x];
        off[i] = o;
        cur[i] = o;
    }
}

__global__ void fill_kernel(const int* __restrict__ src, const int* __restrict__ dst,
                            int* __restrict__ cur, int* __restrict__ esrc, int E) {
    int e = blockIdx.x * blockDim.x + threadIdx.x;
    if (e < E) {
        int p = atomicAdd(&cur[dst[e]], 1);
        esrc[p] = src[e];
    }
}

// ---------------------------------------------------------------------------
// W conversions: combined [k][n] -> n-major bf16 hi/lo wt[n*K + k]
// ---------------------------------------------------------------------------
__global__ void cvt_w_kernel(const float* __restrict__ wl, const float* __restrict__ wr,
                             unsigned short* __restrict__ wth, unsigned short* __restrict__ wtl) {
    int i = blockIdx.x * blockDim.x + threadIdx.x;
    if (i >= 128 * 128) return;
    int nn = i >> 7, k = i & 127;
    float w = (nn < 64) ? wl[k * 64 + nn] : wr[k * 64 + (nn - 64)];
    __nv_bfloat16 h = __float2bfloat16(w);
    __nv_bfloat16 l = __float2bfloat16(w - __bfloat162float(h));
    wth[i] = *reinterpret_cast<unsigned short*>(&h);
    wtl[i] = *reinterpret_cast<unsigned short*>(&l);
}

__global__ void cvt_w1_kernel(const float* __restrict__ wl, const float* __restrict__ wr,
                              unsigned short* __restrict__ wth, unsigned short* __restrict__ wtl) {
    int i = blockIdx.x * blockDim.x + threadIdx.x;
    if (i >= 64 * 64) return;
    int nn = i >> 6, k = i & 63;
    float w = (nn < 32) ? wl[k * 32 + nn] : wr[k * 32 + (nn - 32)];
    __nv_bfloat16 h = __float2bfloat16(w);
    __nv_bfloat16 l = __float2bfloat16(w - __bfloat162float(h));
    wth[i] = *reinterpret_cast<unsigned short*>(&h);
    wtl[i] = *reinterpret_cast<unsigned short*>(&l);
}

// ---------------------------------------------------------------------------
// mma helpers
// ---------------------------------------------------------------------------
__device__ __forceinline__ void mma16816(float* d, const unsigned* a,
                                         unsigned b0, unsigned b1) {
    asm volatile(
        "mma.sync.aligned.m16n8k16.row.col.f32.bf16.bf16.f32 "
        "{%0,%1,%2,%3}, {%4,%5,%6,%7}, {%8,%9}, {%0,%1,%2,%3};"
        : "+f"(d[0]), "+f"(d[1]), "+f"(d[2]), "+f"(d[3])
        : "r"(a[0]), "r"(a[1]), "r"(a[2]), "r"(a[3]), "r"(b0), "r"(b1));
}

__device__ __forceinline__ unsigned pack2_hi(float a, float b) {
    __nv_bfloat162 t;
    t.x = __float2bfloat16(a);
    t.y = __float2bfloat16(b);
    return *reinterpret_cast<unsigned*>(&t);
}

// ---------------------------------------------------------------------------
// layer-0 tensor-core GEMM (persistent): ylr[n x 128] = X[n x 128] @ W[128 x 128]
// ---------------------------------------------------------------------------
__global__ void __launch_bounds__(256, 2)
mma_proj0(const float* __restrict__ x, const unsigned short* __restrict__ wth,
          const unsigned short* __restrict__ wtl, float* __restrict__ ylr,
          int n, int ntiles) {
    constexpr int S = 136;
    extern __shared__ __align__(16) unsigned short smu[];
    unsigned short* sXh = smu;              // [64][S]
    unsigned short* sXl = sXh + 64 * S;
    unsigned short* sWh = sXl + 64 * S;     // n-major [128][S]
    unsigned short* sWl = sWh + 128 * S;

    const int tid = threadIdx.x;
    const int lane = tid & 31;
    const int warp = tid >> 5;
    const int warpm = warp >> 1;
    const int warpn = warp & 1;
    const int g = lane >> 2;
    const int t2 = (lane & 3) * 2;

    for (int idx = tid; idx < 128 * 16; idx += 256) {
        int r = idx >> 4, c = (idx & 15) * 8;
        *reinterpret_cast<uint4*>(&sWh[r * S + c]) =
            *reinterpret_cast<const uint4*>(&wth[r * 128 + c]);
        *reinterpret_cast<uint4*>(&sWl[r * S + c]) =
            *reinterpret_cast<const uint4*>(&wtl[r * 128 + c]);
    }

    float4 xf[8];
    auto load_x = [&](int tile) {
        const int nb = tile * 64;
        const int mrem = n - nb;
#pragma unroll
        for (int i = 0; i < 8; ++i) {
            int idx = tid + i * 256;
            int r = idx >> 5, cc = (idx & 31) * 4;
            float4 v = make_float4(0.f, 0.f, 0.f, 0.f);
            if (r < mrem)
                v = *reinterpret_cast<const float4*>(&x[(size_t)(nb + r) * 128 + cc]);
            xf[i] = v;
        }
    };

    int tile = blockIdx.x;
    if (tile < ntiles) load_x(tile);

    while (tile < ntiles) {
#pragma unroll
        for (int i = 0; i < 8; ++i) {
            int idx = tid + i * 256;
            int r = idx >> 5, cc = (idx & 31) * 4;
            float4 v = xf[i];
            __nv_bfloat16 h0 = __float2bfloat16(v.x), h1 = __float2bfloat16(v.y);
            __nv_bfloat16 h2 = __float2bfloat16(v.z), h3 = __float2bfloat16(v.w);
            uint2 ph, pl;
            __nv_bfloat162 t;
            t.x = h0; t.y = h1; ph.x = *reinterpret_cast<unsigned*>(&t);
            t.x = h2; t.y = h3; ph.y = *reinterpret_cast<unsigned*>(&t);
            pl.x = pack2_hi(v.x - __bfloat162float(h0), v.y - __bfloat162float(h1));
            pl.y = pack2_hi(v.z - __bfloat162float(h2), v.w - __bfloat162float(h3));
            *reinterpret_cast<uint2*>(&sXh[r * S + cc]) = ph;
            *reinterpret_cast<uint2*>(&sXl[r * S + cc]) = pl;
        }
        __syncthreads();

        const int nb = tile * 64;
        const int next = tile + gridDim.x;
        if (next < ntiles) load_x(next);

        float acc[8][4];
#pragma unroll
        for (int nt = 0; nt < 8; ++nt)
#pragma unroll
            for (int t = 0; t < 4; ++t) acc[nt][t] = 0.f;

#pragma unroll
        for (int s = 0; s < 8; ++s) {
            const int k0 = s * 16;
            unsigned ah[4], al[4];
            {
                int r = warpm * 16 + g;
                ah[0] = *reinterpret_cast<const unsigned*>(&sXh[r * S + k0 + t2]);
                ah[1] = *reinterpret_cast<const unsigned*>(&sXh[(r + 8) * S + k0 + t2]);
                ah[2] = *reinterpret_cast<const unsigned*>(&sXh[r * S + k0 + t2 + 8]);
                ah[3] = *reinterpret_cast<const unsigned*>(&sXh[(r + 8) * S + k0 + t2 + 8]);
                al[0] = *reinterpret_cast<const unsigned*>(&sXl[r * S + k0 + t2]);
                al[1] = *reinterpret_cast<const unsigned*>(&sXl[(r + 8) * S + k0 + t2]);
                al[2] = *reinterpret_cast<const unsigned*>(&sXl[r * S + k0 + t2 + 8]);
                al[3] = *reinterpret_cast<const unsigned*>(&sXl[(r + 8) * S + k0 + t2 + 8]);
            }
#pragma unroll
            for (int nt = 0; nt < 8; ++nt) {
                int nn = warpn * 64 + nt * 8 + g;
                unsigned bh0 = *reinterpret_cast<const unsigned*>(&sWh[nn * S + k0 + t2]);
                unsigned bh1 = *reinterpret_cast<const unsigned*>(&sWh[nn * S + k0 + t2 + 8]);
                unsigned bl0 = *reinterpret_cast<const unsigned*>(&sWl[nn * S + k0 + t2]);
                unsigned bl1 = *reinterpret_cast<const unsigned*>(&sWl[nn * S + k0 + t2 + 8]);
                mma16816(acc[nt], ah, bh0, bh1);
                mma16816(acc[nt], al, bh0, bh1);
                mma16816(acc[nt], ah, bl0, bl1);
            }
        }

#pragma unroll
        for (int nt = 0; nt < 8; ++nt) {
            int col = warpn * 64 + nt * 8 + t2;
            int node0 = nb + warpm * 16 + g;
            int node1 = node0 + 8;
            if (node0 < n) {
                float2 v = make_float2(acc[nt][0], acc[nt][1]);
                *reinterpret_cast<float2*>(&ylr[(size_t)node0 * 128 + col]) = v;
            }
            if (node1 < n) {
                float2 v = make_float2(acc[nt][2], acc[nt][3]);
                *reinterpret_cast<float2*>(&ylr[(size_t)node1 * 128 + col]) = v;
            }
        }

        __syncthreads();
        tile = next;
    }
}

// ---------------------------------------------------------------------------
// layer-1 tensor-core GEMM (persistent): ylr[n x 64] = X[n x 64] @ W[64 x 64]
// ---------------------------------------------------------------------------
__global__ void __launch_bounds__(256, 3)
mma_proj1(const float* __restrict__ x, const unsigned short* __restrict__ wth,
          const unsigned short* __restrict__ wtl, float* __restrict__ ylr,
          int n, int ntiles) {
    constexpr int S = 72;
    extern __shared__ __align__(16) unsigned short smu[];
    unsigned short* sXh = smu;              // [64][S]
    unsigned short* sXl = sXh + 64 * S;
    unsigned short* sWh = sXl + 64 * S;     // n-major [64][S]
    unsigned short* sWl = sWh + 64 * S;

    const int tid = threadIdx.x;
    const int lane = tid & 31;
    const int warp = tid >> 5;
    const int warpm = warp >> 1;
    const int warpn = warp & 1;
    const int g = lane >> 2;
    const int t2 = (lane & 3) * 2;

    for (int idx = tid; idx < 64 * 8; idx += 256) {
        int r = idx >> 3, c = (idx & 7) * 8;
        *reinterpret_cast<uint4*>(&sWh[r * S + c]) =
            *reinterpret_cast<const uint4*>(&wth[r * 64 + c]);
        *reinterpret_cast<uint4*>(&sWl[r * S + c]) =
            *reinterpret_cast<const uint4*>(&wtl[r * 64 + c]);
    }

    float4 xf[4];
    auto load_x = [&](int tile) {
        const int nb = tile * 64;
        const int mrem = n - nb;
#pragma unroll
        for (int i = 0; i < 4; ++i) {
            int idx = tid + i * 256;
            int r = idx >> 4, cc = (idx & 15) * 4;
            float4 v = make_float4(0.f, 0.f, 0.f, 0.f);
            if (r < mrem)
                v = *reinterpret_cast<const float4*>(&x[(size_t)(nb + r) * 64 + cc]);
            xf[i] = v;
        }
    };

    int tile = blockIdx.x;
    if (tile < ntiles) load_x(tile);

    while (tile < ntiles) {
#pragma unroll
        for (int i = 0; i < 4; ++i) {
            int idx = tid + i * 256;
            int r = idx >> 4, cc = (idx & 15) * 4;
            float4 v = xf[i];
            __nv_bfloat16 h0 = __float2bfloat16(v.x), h1 = __float2bfloat16(v.y);
            __nv_bfloat16 h2 = __float2bfloat16(v.z), h3 = __float2bfloat16(v.w);
            uint2 ph, pl;
            __nv_bfloat162 t;
            t.x = h0; t.y = h1; ph.x = *reinterpret_cast<unsigned*>(&t);
            t.x = h2; t.y = h3; ph.y = *reinterpret_cast<unsigned*>(&t);
            pl.x = pack2_hi(v.x - __bfloat162float(h0), v.y - __bfloat162float(h1));
            pl.y = pack2_hi(v.z - __bfloat162float(h2), v.w - __bfloat162float(h3));
            *reinterpret_cast<uint2*>(&sXh[r * S + cc]) = ph;
            *reinterpret_cast<uint2*>(&sXl[r * S + cc]) = pl;
        }
        __syncthreads();

        const int nb = tile * 64;
        const int next = tile + gridDim.x;
        if (next < ntiles) load_x(next);

        float acc[4][4];
#pragma unroll
        for (int nt = 0; nt < 4; ++nt)
#pragma unroll
            for (int t = 0; t < 4; ++t) acc[nt][t] = 0.f;

#pragma unroll
        for (int s = 0; s < 4; ++s) {
            const int k0 = s * 16;
            unsigned ah[4], al[4];
            {
                int r = warpm * 16 + g;
                ah[0] = *reinterpret_cast<const unsigned*>(&sXh[r * S + k0 + t2]);
                ah[1] = *reinterpret_cast<const unsigned*>(&sXh[(r + 8) * S + k0 + t2]);
                ah[2] = *reinterpret_cast<const unsigned*>(&sXh[r * S + k0 + t2 + 8]);
                ah[3] = *reinterpret_cast<const unsigned*>(&sXh[(r + 8) * S + k0 + t2 + 8]);
                al[0] = *reinterpret_cast<const unsigned*>(&sXl[r * S + k0 + t2]);
                al[1] = *reinterpret_cast<const unsigned*>(&sXl[(r + 8) * S + k0 + t2]);
                al[2] = *reinterpret_cast<const unsigned*>(&sXl[r * S + k0 + t2 + 8]);
                al[3] = *reinterpret_cast<const unsigned*>(&sXl[(r + 8) * S + k0 + t2 + 8]);
            }
#pragma unroll
            for (int nt = 0; nt < 4; ++nt) {
                int nn = warpn * 32 + nt * 8 + g;
                unsigned bh0 = *reinterpret_cast<const unsigned*>(&sWh[nn * S + k0 + t2]);
                unsigned bh1 = *reinterpret_cast<const unsigned*>(&sWh[nn * S + k0 + t2 + 8]);
                unsigned bl0 = *reinterpret_cast<const unsigned*>(&sWl[nn * S + k0 + t2]);
                unsigned bl1 = *reinterpret_cast<const unsigned*>(&sWl[nn * S + k0 + t2 + 8]);
                mma16816(acc[nt], ah, bh0, bh1);
                mma16816(acc[nt], al, bh0, bh1);
                mma16816(acc[nt], ah, bl0, bl1);
            }
        }

#pragma unroll
        for (int nt = 0; nt < 4; ++nt) {
            int col = warpn * 32 + nt * 8 + t2;
            int node0 = nb + warpm * 16 + g;
            int node1 = node0 + 8;
            if (node0 < n) {
                float2 v = make_float2(acc[nt][0], acc[nt][1]);
                *reinterpret_cast<float2*>(&ylr[(size_t)node0 * 64 + col]) = v;
            }
            if (node1 < n) {
                float2 v = make_float2(acc[nt][2], acc[nt][3]);
                *reinterpret_cast<float2*>(&ylr[(size_t)node1 * 64 + col]) = v;
            }
        }

        __syncthreads();
        tile = next;
    }
}

// ---------------------------------------------------------------------------
// per-node projection for small layers
// ---------------------------------------------------------------------------
template <int K, int F>
__global__ void proj_pernode(const float* __restrict__ x, const float* __restrict__ wl,
                             const float* __restrict__ wr, float* __restrict__ ylr, int n) {
    constexpr int NC = 2 * F;
    __shared__ float sB[K * NC];
    for (int i = threadIdx.x; i < K * NC; i += blockDim.x) {
        int k = i / NC, j = i % NC;
        sB[i] = (j < F) ? wl[k * F + j] : wr[k * F + (j - F)];
    }
    __syncthreads();

    int node = blockIdx.x * blockDim.x + threadIdx.x;
    if (node >= n) return;

    float xv[K];
    const float4* xr = reinterpret_cast<const float4*>(x + (size_t)node * K);
#pragma unroll
    for (int c = 0; c < K / 4; ++c) {
        float4 v = xr[c];
        xv[c * 4 + 0] = v.x; xv[c * 4 + 1] = v.y; xv[c * 4 + 2] = v.z; xv[c * 4 + 3] = v.w;
    }
    float acc[NC];
#pragma unroll
    for (int j = 0; j < NC; ++j) acc[j] = 0.f;
#pragma unroll
    for (int k = 0; k < K; ++k) {
        float a = xv[k];
#pragma unroll
        for (int j = 0; j < NC; ++j) acc[j] = fmaf(a, sB[k * NC + j], acc[j]);
    }
    float4* o = reinterpret_cast<float4*>(ylr + (size_t)node * NC);
#pragma unroll
    for (int c = 0; c < NC / 4; ++c)
        o[c] = make_float4(acc[c * 4], acc[c * 4 + 1], acc[c * 4 + 2], acc[c * 4 + 3]);
}

__global__ void proj3_pernode(const float* __restrict__ x, const float* __restrict__ wl,
                              const float* __restrict__ wr, float* __restrict__ ylr3, int n) {
    __shared__ float swl[16 * 9];
    __shared__ float swr[16 * 9];
    for (int i = threadIdx.x; i < 144; i += blockDim.x) {
        swl[i] = wl[i];
        swr[i] = wr[i];
    }
    __syncthreads();

    int node = blockIdx.x * blockDim.x + threadIdx.x;
    if (node >= n) return;

    float xv[16];
    const float4* xr = reinterpret_cast<const float4*>(x + (size_t)node * 16);
#pragma unroll
    for (int c = 0; c < 4; ++c) {
        float4 v = xr[c];
        xv[c * 4 + 0] = v.x; xv[c * 4 + 1] = v.y; xv[c * 4 + 2] = v.z; xv[c * 4 + 3] = v.w;
    }
    float al[9], ar[9];
#pragma unroll
    for (int j = 0; j < 9; ++j) { al[j] = 0.f; ar[j] = 0.f; }
#pragma unroll
    for (int k = 0; k < 16; ++k) {
        float a = xv[k];
#pragma unroll
        for (int j = 0; j < 9; ++j) {
            al[j] = fmaf(a, swl[k * 9 + j], al[j]);
            ar[j] = fmaf(a, swr[k * 9 + j], ar[j]);
        }
    }
    float4* o = reinterpret_cast<float4*>(ylr3 + (size_t)node * 32);
    o[0] = make_float4(al[0], al[1], al[2], al[3]);
    o[1] = make_float4(al[4], al[5], al[6], al[7]);
    o[2] = make_float4(al[8], 0.f, 0.f, 0.f);
    o[3] = make_float4(0.f, 0.f, 0.f, 0.f);
    o[4] = make_float4(ar[0], ar[1], ar[2], ar[3]);
    o[5] = make_float4(ar[4], ar[5], ar[6], ar[7]);
    ylr3[(size_t)node * 32 + 24] = ar[8];
}

// ---------------------------------------------------------------------------
// gather + combine (fused): warp per node, edge indices preloaded into lanes
// and distributed via shfl -> independent y4 loads (high MLP).
// ---------------------------------------------------------------------------
template <int F, bool RELU>
__global__ void gather_combine(const float* __restrict__ ylr, const int* __restrict__ esrc,
                               const int* __restrict__ off, const int* __restrict__ cnt,
                               const float* __restrict__ bias, float* __restrict__ out, int n) {
    constexpr int CH = F / 4;
    constexpr int EPW = 32 / CH;
    int w = (blockIdx.x * blockDim.x + threadIdx.x) >> 5;
    if (w >= n) return;
    int lane = threadIdx.x & 31;
    int c = lane % CH, g = lane / CH;
    int start = __ldg(off + w), deg = __ldg(cnt + w);

    // preload up to 32 edge indices (one per lane, coalesced)
    int eidx = 0;
    if (lane < deg) eidx = __ldg(esrc + start + lane);

    float4 acc = make_float4(0.f, 0.f, 0.f, 0.f);
    const float4* y4 = reinterpret_cast<const float4*>(ylr);
    int dmain = deg < 32 ? deg : 32;

    // uniform loop bound -> shfl executed by all lanes; load predicated
#pragma unroll 4
    for (int j = 0; j < dmain; j += EPW) {
        int jj = j + g;
        int src_lane = jj < 31 ? jj : 31;
        int s = __shfl_sync(0xFFFFFFFFu, eidx, src_lane);
        if (jj < dmain) {
            float4 v = y4[(size_t)s * (F / 2) + c];
            acc.x += v.x; acc.y += v.y; acc.z += v.z; acc.w += v.w;
        }
    }
    // rare tail: deg > 32
    for (int j = 32 + g; j < deg; j += EPW) {
        int s = __ldg(esrc + start + j);
        float4 v = y4[(size_t)s * (F / 2) + c];
        acc.x += v.x; acc.y += v.y; acc.z += v.z; acc.w += v.w;
    }

#pragma unroll
    for (int st = 16; st >= CH; st >>= 1) {
        acc.x += __shfl_xor_sync(0xFFFFFFFFu, acc.x, st);
        acc.y += __shfl_xor_sync(0xFFFFFFFFu, acc.y, st);
        acc.z += __shfl_xor_sync(0xFFFFFFFFu, acc.z, st);
        acc.w += __shfl_xor_sync(0xFFFFFFFFu, acc.w, st);
    }
    if (lane < CH) {
        float iv = __frcp_rn(fmaxf((float)deg, 1.0f));
        float4 r = y4[(size_t)w * (F / 2) + (F / 4) + c];
        float4 b = reinterpret_cast<const float4*>(bias)[c];
        float4 v;
        v.x = fmaf(acc.x, iv, r.x) + b.x;
        v.y = fmaf(acc.y, iv, r.y) + b.y;
        v.z = fmaf(acc.z, iv, r.z) + b.z;
        v.w = fmaf(acc.w, iv, r.w) + b.w;
        if (RELU) {
            v.x = fmaxf(v.x, 0.f); v.y = fmaxf(v.y, 0.f);
            v.z = fmaxf(v.z, 0.f); v.w = fmaxf(v.w, 0.f);
        }
        reinterpret_cast<float4*>(out)[(size_t)w * CH + c] = v;
    }
}

__global__ void gather9(const float* __restrict__ ylr3, const int* __restrict__ esrc,
                        const int* __restrict__ off, const int* __restrict__ cnt,
                        const float* __restrict__ bias, float* __restrict__ out, int n) {
    int w = (blockIdx.x * blockDim.x + threadIdx.x) >> 5;
    if (w >= n) return;
    int lane = threadIdx.x & 31;
    int c = lane % 4, g = lane / 4;  // 8 edges per iter
    int start = __ldg(off + w), deg = __ldg(cnt + w);

    int eidx = 0;
    if (lane < deg) eidx = __ldg(esrc + start + lane);

    float4 acc = make_float4(0.f, 0.f, 0.f, 0.f);
    const float4* y4 = reinterpret_cast<const float4*>(ylr3);
    int dmain = deg < 32 ? deg : 32;

#pragma unroll 2
    for (int j = 0; j < dmain; j += 8) {
        int jj = j + g;
        int src_lane = jj < 31 ? jj : 31;
        int s = __shfl_sync(0xFFFFFFFFu, eidx, src_lane);
        if (jj < dmain) {
            float4 v = y4[(size_t)s * 8 + c];
            acc.x += v.x; acc.y += v.y; acc.z += v.z; acc.w += v.w;
        }
    }
    for (int j = 32 + g; j < deg; j += 8) {
        int s = __ldg(esrc + start + j);
        float4 v = y4[(size_t)s * 8 + c];
        acc.x += v.x; acc.y += v.y; acc.z += v.z; acc.w += v.w;
    }

#pragma unroll
    for (int st = 16; st >= 4; st >>= 1) {
        acc.x += __shfl_xor_sync(0xFFFFFFFFu, acc.x, st);
        acc.y += __shfl_xor_sync(0xFFFFFFFFu, acc.y, st);
        acc.z += __shfl_xor_sync(0xFFFFFFFFu, acc.z, st);
        acc.w += __shfl_xor_sync(0xFFFFFFFFu, acc.w, st);
    }
    if (lane < 4) {
        float iv = __frcp_rn(fmaxf((float)deg, 1.0f));
        float a[4] = {acc.x, acc.y, acc.z, acc.w};
#pragma unroll
        for (int t = 0; t < 4; ++t) {
            int j = c * 4 + t;
            if (j < 9) {
                float yr = ylr3[(size_t)w * 32 + 16 + j];
                out[(size_t)w * 9 + j] = fmaf(a[t], iv, yr + __ldg(bias + j));
            }
        }
    }
}

// ---------------------------------------------------------------------------
// launch
// ---------------------------------------------------------------------------
extern "C" void kernel_launch(void* const* d_in, const int* in_sizes, int n_in,
                              void* d_out, int out_size) {
    const float* emb = (const float*)d_in[0];
    const int* ei = (const int*)d_in[1];
    const float* wl0 = (const float*)d_in[3];
    const float* wr0 = (const float*)d_in[4];
    const float* b0  = (const float*)d_in[5];
    const float* wl1 = (const float*)d_in[6];
    const float* wr1 = (const float*)d_in[7];
    const float* b1  = (const float*)d_in[8];
    const float* wl2 = (const float*)d_in[9];
    const float* wr2 = (const float*)d_in[10];
    const float* b2  = (const float*)d_in[11];
    const float* wl3 = (const float*)d_in[12];
    const float* wr3 = (const float*)d_in[13];
    const float* b3  = (const float*)d_in[14];
    float* out = (float*)d_out;

    const int n = in_sizes[0] / 128;
    const int E = in_sizes[1] / 2;
    const int* src = ei;
    const int* dst = ei + E;

    float *ylr, *xbuf;
    unsigned short *wth, *wtl, *wth1, *wtl1;
    int *cnt, *off, *cur, *esrc, *bsum;
    cudaGetSymbolAddress((void**)&ylr, g_ylr);
    cudaGetSymbolAddress((void**)&xbuf, g_x);
    cudaGetSymbolAddress((void**)&wth, g_wth);
    cudaGetSymbolAddress((void**)&wtl, g_wtl);
    cudaGetSymbolAddress((void**)&wth1, g_wth1);
    cudaGetSymbolAddress((void**)&wtl1, g_wtl1);
    cudaGetSymbolAddress((void**)&cnt, g_cnt);
    cudaGetSymbolAddress((void**)&off, g_off);
    cudaGetSymbolAddress((void**)&cur, g_cur);
    cudaGetSymbolAddress((void**)&esrc, g_esrc);
    cudaGetSymbolAddress((void**)&bsum, g_bsum);

    auto cdiv = [](int a, int b) { return (a + b - 1) / b; };
    const int TB = 256;
    const int nb = cdiv(n, 512);

    const int SM_MMA0 = (2 * 64 * 136 + 2 * 128 * 136) * 2;  // 104448
    const int SM_MMA1 = (4 * 64 * 72) * 2;                   // 36864
    cudaFuncSetAttribute((const void*)mma_proj0,
                         cudaFuncAttributeMaxDynamicSharedMemorySize, SM_MMA0);
    cudaFuncSetAttribute((const void*)mma_proj1,
                         cudaFuncAttributeMaxDynamicSharedMemorySize, SM_MMA1);

    static cudaStream_t s2 = nullptr;
    static cudaEvent_t evFork = nullptr, evJoin = nullptr;
    if (!s2) {
        cudaStreamCreateWithFlags(&s2, cudaStreamNonBlocking);
        cudaEventCreateWithFlags(&evFork, cudaEventDisableTiming);
        cudaEventCreateWithFlags(&evJoin, cudaEventDisableTiming);
    }

    // ---- fork: CSR build + W1 conversion on s2 (hidden under proj0) ----
    cudaEventRecord(evFork, 0);
    cudaStreamWaitEvent(s2, evFork, 0);

    cvt_w1_kernel<<<16, 256, 0, s2>>>(wl1, wr1, wth1, wtl1);
    zero_int<<<cdiv(n, 512), 512, 0, s2>>>(cnt, n);
    hist_kernel<<<cdiv(E, 512), 512, 0, s2>>>(dst, cnt, E);
    scan_block<<<nb, 512, 0, s2>>>(cnt, off, bsum, n);
    scan_sums<<<1, 512, 0, s2>>>(bsum, nb);
    scan_add<<<nb, 512, 0, s2>>>(off, bsum, cur, n);
    fill_kernel<<<cdiv(E, 512), 512, 0, s2>>>(src, dst, cur, esrc, E);
    cudaEventRecord(evJoin, s2);

    // ---- main: layer-0 tensor-core GEMM (persistent) ----
    cvt_w_kernel<<<64, 256>>>(wl0, wr0, wth, wtl);
    mma_proj0<<<296, 256, SM_MMA0>>>(emb, wth, wtl, ylr, n, cdiv(n, 64));

    // ---- join ----
    cudaStreamWaitEvent(0, evJoin, 0);

    gather_combine<64, true><<<cdiv(n * 32, TB), TB>>>(ylr, esrc, off, cnt, b0, xbuf, n);

    mma_proj1<<<444, 256, SM_MMA1>>>(xbuf, wth1, wtl1, ylr, n, cdiv(n, 64));
    gather_combine<32, true><<<cdiv(n * 32, TB), TB>>>(ylr, esrc, off, cnt, b1, xbuf, n);

    proj_pernode<32, 16><<<cdiv(n, TB), TB>>>(xbuf, wl2, wr2, ylr, n);
    gather_combine<16, true><<<cdiv(n * 32, TB), TB>>>(ylr, esrc, off, cnt, b2, xbuf, n);

    proj3_pernode<<<cdiv(n, TB), TB>>>(xbuf, wl3, wr3, ylr, n);
    gather9<<<cdiv(n * 32, TB), TB>>>(ylr, esrc, off, cnt, b3, out, n);
}